// round 3
// baseline (speedup 1.0000x reference)
#include <cuda_runtime.h>
#include <math.h>

#define FD    1024
#define SEM   300
#define NWAY  5
#define BS    32
#define NB    512
#define NQ    75
#define BTOT  (BS*NWAY)     // 160
#define CATD  (FD+SEM)      // 1324

// ---------------- scratch (device globals) ----------------
__device__ float g_scal[BTOT*SEM];
__device__ float g_avg [BS*CATD];
__device__ float g_gv  [BS*FD];
__device__ float g_gs  [BS*SEM];
__device__ float g_q   [BTOT*FD];
__device__ float g_qkg [BTOT*FD];
__device__ float g_qksg[BTOT*SEM];
__device__ float g_scr [BTOT*NB];
__device__ float g_mix [BTOT*FD];
__device__ float g_outv[BTOT*FD];
__device__ float g_out [BTOT*FD];
__device__ float g_BT  [FD*CATD];
__device__ float g_fake[BS*FD];
__device__ float g_pinv[BS*6];
__device__ float g_part [26*BTOT*FD];     // split-K partials (q: 26 slots of 160x1024)
__device__ float g_part2[42*BS*CATD];     // gates partials
__device__ unsigned int g_barrier;

// ---------------- software grid barrier ----------------
__device__ __forceinline__ void gsync(int &gen)
{
    __syncthreads();
    if (threadIdx.x == 0) {
        __threadfence();
        atomicAdd(&g_barrier, 1u);
        unsigned target = (unsigned)gridDim.x * (unsigned)gen;
        unsigned v;
        do {
            asm volatile("ld.acquire.gpu.u32 %0, [%1];" : "=r"(v) : "l"(&g_barrier) : "memory");
            if (v >= target) break;
            __nanosleep(32);
        } while (true);
    }
    __syncthreads();
    gen++;
}

// ---------------- split-K GEMM partial (famA-style, device fn) ----------------
// part[(zbase+z)*M*N + m*N + n] = A[m, kchunk_z] @ B[kchunk_z, n]
// B column: n<N1 -> B1 (row stride N1), else B2 (row stride N-N1)
__device__ __forceinline__ void gemm_part(
    const float* __restrict__ A, int M, int K,
    const float* __restrict__ B1, const float* __restrict__ B2, int N1, int N,
    float* __restrict__ part, int zbase, int tpz, int Z, int nch,
    int u, float* smA)
{
    int z = u % Z;  int r = u / Z;
    int n0 = (r % nch) * 256;
    int m0 = (r / nch) * 32;
    int n  = n0 + threadIdx.x;
    int kbeg = z * tpz * 32;
    int kend = min(K, kbeg + tpz * 32);
    float acc[32];
#pragma unroll
    for (int i = 0; i < 32; i++) acc[i] = 0.f;
    bool nok = (n < N);
    const float* bcol; int bstr;
    if (n < N1) { bcol = B1 + n;        bstr = N1;     }
    else        { bcol = B2 + (n - N1); bstr = N - N1; }

    for (int k0 = kbeg; k0 < kend; k0 += 32) {
#pragma unroll
        for (int e = 0; e < 4; e++) {
            int idx = threadIdx.x + e*256;
            int mm = idx >> 5, kk = idx & 31;
            int mg = m0 + mm, kg = k0 + kk;
            smA[kk*33 + mm] = (mg < M && kg < K) ? A[(size_t)mg*K + kg] : 0.f;
        }
        __syncthreads();
        if (nok) {
            const float* bp = bcol + (size_t)k0 * bstr;
            int kmax = min(32, kend - k0);
            for (int kk = 0; kk < kmax; kk++) {
                float w = bp[(size_t)kk * bstr];
                const float* ar = &smA[kk*33];
#pragma unroll
                for (int rr = 0; rr < 32; rr++) acc[rr] = fmaf(w, ar[rr], acc[rr]);
            }
        }
        __syncthreads();
    }
    if (nok) {
        size_t base = (size_t)(zbase + z) * M * N + n;
#pragma unroll
        for (int rr = 0; rr < 32; rr++) {
            int m = m0 + rr;
            if (m < M) part[base + (size_t)m*N] = acc[rr];
        }
    }
}

__device__ __forceinline__ float psum(const float* __restrict__ part, int Z, size_t MN, size_t i)
{
    float v = 0.f;
    for (int z = 0; z < Z; z++) v += part[(size_t)z*MN + i];
    return v;
}

__device__ __forceinline__ float d4(float4 a, float4 b)
{ return a.x*b.x + a.y*b.y + a.z*b.z + a.w*b.w; }

// stage unit counts
#define U_MLP  40
#define U_QP1  320
#define U_AVG  166
#define U_TR   1344
#define S0U    (U_MLP+U_QP1+U_AVG+U_TR)   // 1870
#define U_QP2  200
#define U_GP   252
#define S1U    (U_QP2+U_GP)
#define U_QR   640
#define U_GR   166
#define S2U    (U_QR+U_GR)

__global__ void __launch_bounds__(256, 2) fused_k(
    const float* __restrict__ sc,  const float* __restrict__ bw,
    const float* __restrict__ ss,  const float* __restrict__ bsm,
    const float* __restrict__ qf,
    const float* __restrict__ Wm1, const float* __restrict__ bm1,
    const float* __restrict__ Wm2, const float* __restrict__ bm2,
    const float* __restrict__ Wvis,const float* __restrict__ bvis,
    const float* __restrict__ Wsem,const float* __restrict__ bsem,
    const float* __restrict__ Wq,  const float* __restrict__ Wk,
    const float* __restrict__ Wv,  const float* __restrict__ Wqs,
    const float* __restrict__ Wks, const float* __restrict__ Wfc,
    const float* __restrict__ temp, float* __restrict__ outL)
{
    __shared__ float sm[2560];
    const int NBLK = gridDim.x;
    const int t = threadIdx.x;
    int gen = 1;

    // ============ S0: MLP (fused 2-layer) | q-part1 (sc@Wq) | avg | BT transpose ============
    for (int u = blockIdx.x; u < S0U; u += NBLK) {
        if (u < U_MLP) {
            // ---- fused map_sem MLP, 4 rows per unit ----
            int m0u = u * 4;
            for (int i = t; i < 4*SEM; i += 256)
                sm[i] = ss[(size_t)(m0u + i/SEM)*SEM + (i % SEM)];
            __syncthreads();
            for (int n = t; n < SEM; n += 256) {
                float a0 = bm1[n], a1 = a0, a2 = a0, a3 = a0;
                for (int k = 0; k < SEM; k++) {
                    float w = Wm1[(size_t)k*SEM + n];
                    a0 = fmaf(sm[0*SEM+k], w, a0); a1 = fmaf(sm[1*SEM+k], w, a1);
                    a2 = fmaf(sm[2*SEM+k], w, a2); a3 = fmaf(sm[3*SEM+k], w, a3);
                }
                sm[4*SEM + 0*SEM + n] = (a0 >= 0.f) ? a0 : 0.1f*a0;
                sm[4*SEM + 1*SEM + n] = (a1 >= 0.f) ? a1 : 0.1f*a1;
                sm[4*SEM + 2*SEM + n] = (a2 >= 0.f) ? a2 : 0.1f*a2;
                sm[4*SEM + 3*SEM + n] = (a3 >= 0.f) ? a3 : 0.1f*a3;
            }
            __syncthreads();
            for (int n = t; n < SEM; n += 256) {
                float a0 = bm2[n], a1 = a0, a2 = a0, a3 = a0;
                for (int k = 0; k < SEM; k++) {
                    float w = Wm2[(size_t)k*SEM + n];
                    a0 = fmaf(sm[4*SEM+0*SEM+k], w, a0); a1 = fmaf(sm[4*SEM+1*SEM+k], w, a1);
                    a2 = fmaf(sm[4*SEM+2*SEM+k], w, a2); a3 = fmaf(sm[4*SEM+3*SEM+k], w, a3);
                }
                g_scal[(size_t)(m0u+0)*SEM + n] = a0;
                g_scal[(size_t)(m0u+1)*SEM + n] = a1;
                g_scal[(size_t)(m0u+2)*SEM + n] = a2;
                g_scal[(size_t)(m0u+3)*SEM + n] = a3;
            }
            __syncthreads();
        } else if (u < U_MLP + U_QP1) {
            gemm_part(sc, BTOT, FD, Wq, Wq, FD, FD, g_part, 0, 2, 16, 4, u - U_MLP, sm);
        } else if (u < U_MLP + U_QP1 + U_AVG) {
            int i = (u - (U_MLP+U_QP1))*256 + t;
            if (i < BS*CATD) {
                int b = i / CATD, c = i % CATD;
                float s = 0.f;
                if (c < FD) {
                    const float* p = bw + (size_t)b*NB*FD + c;
#pragma unroll 8
                    for (int n = 0; n < NB; n++) s += p[(size_t)n*FD];
                } else {
                    const float* p = bsm + (size_t)b*NB*SEM + (c - FD);
#pragma unroll 8
                    for (int n = 0; n < NB; n++) s += p[(size_t)n*SEM];
                }
                g_avg[b*CATD + c] = s * (1.f/NB);
            }
        } else {
            // ---- BT transpose: BT[k][n] = [Wk;Wks]^T ----
            int uu = u - (U_MLP+U_QP1+U_AVG);
            int k0 = (uu / 42) * 32, n0 = (uu % 42) * 32;
            int lx = t & 31, ly = t >> 5;
            for (int i = ly; i < 32; i += 8) {
                int n = n0 + i, k = k0 + lx;
                float v = 0.f;
                if (n < CATD) v = (n < FD) ? Wk[(size_t)n*FD + k] : Wks[(size_t)(n-FD)*FD + k];
                sm[i*33 + lx] = v;
            }
            __syncthreads();
            for (int i = ly; i < 32; i += 8) {
                int k = k0 + i, n = n0 + lx;
                if (n < CATD) g_BT[(size_t)k*CATD + n] = sm[lx*33 + i];
            }
            __syncthreads();
        }
    }
    gsync(gen);

    // ============ S1: q-part2 (s@Wqs) | gates partials ============
    for (int u = blockIdx.x; u < S1U; u += NBLK) {
        if (u < U_QP2)
            gemm_part(g_scal, BTOT, SEM, Wqs, Wqs, FD, FD, g_part, 16, 1, 10, 4, u, sm);
        else
            gemm_part(g_avg, BS, CATD, Wvis, Wsem, FD, CATD, g_part2, 0, 1, 42, 6, u - U_QP2, sm);
    }
    gsync(gen);

    // ============ S2: q reduce | gates reduce ============
    for (int u = blockIdx.x; u < S2U; u += NBLK) {
        if (u < U_QR) {
            size_t i = (size_t)u*256 + t;
            if (i < (size_t)BTOT*FD) g_q[i] = psum(g_part, 26, (size_t)BTOT*FD, i);
        } else {
            size_t i = (size_t)(u - U_QR)*256 + t;
            if (i < (size_t)BS*CATD) {
                int m = (int)(i / CATD), n = (int)(i % CATD);
                float v = psum(g_part2, 42, (size_t)BS*CATD, i);
                if (n < FD) {
                    v += bvis[n];
                    g_gv[(size_t)m*FD + n] = 1.f + 1.f/(1.f + __expf(-v));
                } else {
                    v += bsem[n - FD];
                    g_gs[(size_t)m*SEM + (n - FD)] = 1.f + 1.f/(1.f + __expf(-v));
                }
            }
        }
    }
    gsync(gen);

    // ============ S3: qk partials (q @ BT) ============
    for (int u = blockIdx.x; u < 480; u += NBLK)
        gemm_part(g_q, BTOT, FD, g_BT, g_BT, CATD, CATD, g_part, 0, 2, 16, 6, u, sm);
    gsync(gen);

    // ============ S4: qk reduce * gates ============
    for (int u = blockIdx.x; u < 828; u += NBLK) {
        size_t i = (size_t)u*256 + t;
        if (i < (size_t)BTOT*CATD) {
            int m = (int)(i / CATD), n = (int)(i % CATD);
            float v = psum(g_part, 16, (size_t)BTOT*CATD, i);
            int b = m / NWAY;
            if (n < FD) g_qkg [(size_t)m*FD  + n]      = v * g_gv[(size_t)b*FD  + n];
            else        g_qksg[(size_t)m*SEM + (n-FD)] = v * g_gs[(size_t)b*SEM + (n-FD)];
        }
    }
    gsync(gen);

    // ============ S5: scores ============
    for (int u = blockIdx.x; u < 512; u += NBLK) {
        int b = u / 16, ch = u % 16;
        int w = t >> 5, lane = t & 31;
        int nbase = ch*32 + w*4;
        float acc[4][5];
#pragma unroll
        for (int j = 0; j < 4; j++)
#pragma unroll
            for (int p = 0; p < 5; p++) acc[j][p] = 0.f;
        const float4* qkg4 = (const float4*)g_qkg  + (size_t)b*NWAY*(FD/4);
        const float4* qks4 = (const float4*)g_qksg + (size_t)b*NWAY*(SEM/4);
        const float4* bw4  = (const float4*)bw     + (size_t)b*NB*(FD/4);
        const float4* bs4  = (const float4*)bsm    + (size_t)b*NB*(SEM/4);
#pragma unroll
        for (int tt = 0; tt < 8; tt++) {
            int c = tt*32 + lane;
            float4 qv[5];
#pragma unroll
            for (int p = 0; p < 5; p++) qv[p] = qkg4[p*(FD/4) + c];
#pragma unroll
            for (int j = 0; j < 4; j++) {
                float4 x = bw4[(size_t)(nbase+j)*(FD/4) + c];
#pragma unroll
                for (int p = 0; p < 5; p++) acc[j][p] += d4(x, qv[p]);
            }
        }
#pragma unroll
        for (int tt = 0; tt < 3; tt++) {
            int c = tt*32 + lane;
            bool ok = c < (SEM/4);
            float4 qv[5];
#pragma unroll
            for (int p = 0; p < 5; p++)
                qv[p] = ok ? qks4[p*(SEM/4) + c] : make_float4(0,0,0,0);
#pragma unroll
            for (int j = 0; j < 4; j++) {
                float4 x = ok ? bs4[(size_t)(nbase+j)*(SEM/4) + c] : make_float4(0,0,0,0);
#pragma unroll
                for (int p = 0; p < 5; p++) acc[j][p] += d4(x, qv[p]);
            }
        }
#pragma unroll
        for (int off = 16; off; off >>= 1)
#pragma unroll
            for (int j = 0; j < 4; j++)
#pragma unroll
                for (int p = 0; p < 5; p++)
                    acc[j][p] += __shfl_xor_sync(0xffffffffu, acc[j][p], off);
#pragma unroll
        for (int j = 0; j < 4; j++)
            if (lane == j) {
                int n = nbase + j;
#pragma unroll
                for (int p = 0; p < 5; p++)
                    g_scr[(size_t)(b*NWAY+p)*NB + n] = acc[j][p] * (1.f/32.f);
            }
    }
    gsync(gen);

    // ============ S6: softmax over 512 ============
    for (int u = blockIdx.x; u < BTOT; u += NBLK) {
        float v0 = g_scr[(size_t)u*NB + t], v1 = g_scr[(size_t)u*NB + 256 + t];
        sm[t] = fmaxf(v0, v1); __syncthreads();
        for (int s = 128; s; s >>= 1) { if (t < s) sm[t] = fmaxf(sm[t], sm[t+s]); __syncthreads(); }
        float mx = sm[0]; __syncthreads();
        float e0 = __expf(v0 - mx), e1 = __expf(v1 - mx);
        sm[t] = e0 + e1; __syncthreads();
        for (int s = 128; s; s >>= 1) { if (t < s) sm[t] += sm[t+s]; __syncthreads(); }
        float inv = 1.f / sm[0]; __syncthreads();
        g_scr[(size_t)u*NB + t] = e0*inv;
        g_scr[(size_t)u*NB + 256 + t] = e1*inv;
    }
    gsync(gen);

    // ============ S7: mix ============
    for (int u = blockIdx.x; u < 128; u += NBLK) {
        int b = u / 4, fc = u % 4;
        for (int i = t; i < NWAY*NB; i += 256)
            sm[i] = g_scr[(size_t)b*NWAY*NB + i];
        __syncthreads();
        int f = fc*256 + t;
        float a0=0,a1=0,a2=0,a3=0,a4=0;
        const float* p = bw + (size_t)b*NB*FD + f;
#pragma unroll 8
        for (int n = 0; n < NB; n++) {
            float x = p[(size_t)n*FD];
            a0 = fmaf(x, sm[0*NB+n], a0); a1 = fmaf(x, sm[1*NB+n], a1);
            a2 = fmaf(x, sm[2*NB+n], a2); a3 = fmaf(x, sm[3*NB+n], a3);
            a4 = fmaf(x, sm[4*NB+n], a4);
        }
        float g = g_gv[(size_t)b*FD + f];
        g_mix[(size_t)(b*NWAY+0)*FD + f] = a0*g;
        g_mix[(size_t)(b*NWAY+1)*FD + f] = a1*g;
        g_mix[(size_t)(b*NWAY+2)*FD + f] = a2*g;
        g_mix[(size_t)(b*NWAY+3)*FD + f] = a3*g;
        g_mix[(size_t)(b*NWAY+4)*FD + f] = a4*g;
        __syncthreads();
    }
    gsync(gen);

    // ============ S8: outv partials (mix@Wv) ============
    for (int u = blockIdx.x; u < 320; u += NBLK)
        gemm_part(g_mix, BTOT, FD, Wv, Wv, FD, FD, g_part, 0, 2, 16, 4, u, sm);
    gsync(gen);

    // ============ S9: outv reduce ============
    for (int u = blockIdx.x; u < 640; u += NBLK) {
        size_t i = (size_t)u*256 + t;
        if (i < (size_t)BTOT*FD) g_outv[i] = psum(g_part, 16, (size_t)BTOT*FD, i);
    }
    gsync(gen);

    // ============ S10: out partials (outv@Wfc) ============
    for (int u = blockIdx.x; u < 320; u += NBLK)
        gemm_part(g_outv, BTOT, FD, Wfc, Wfc, FD, FD, g_part, 0, 2, 16, 4, u, sm);
    gsync(gen);

    // ============ S11: out reduce + residual ============
    for (int u = blockIdx.x; u < 640; u += NBLK) {
        size_t i = (size_t)u*256 + t;
        if (i < (size_t)BTOT*FD) g_out[i] = psum(g_part, 16, (size_t)BTOT*FD, i) + sc[i];
    }
    gsync(gen);

    // ============ S12: fake proto + norms ============
    for (int u = blockIdx.x; u < BS; u += NBLK) {
        int b = u;
        const float4* sc4 = (const float4*)sc    + (size_t)b*NWAY*(FD/4);
        const float4* o4  = (const float4*)g_out + (size_t)b*NWAY*(FD/4);
        float4 f = make_float4(0,0,0,0);
#pragma unroll
        for (int r = 0; r < NWAY; r++) {
            float4 v = o4[r*(FD/4) + t];
            f.x += v.x; f.y += v.y; f.z += v.z; f.w += v.w;
        }
        f.x *= 0.2f; f.y *= 0.2f; f.z *= 0.2f; f.w *= 0.2f;
        ((float4*)g_fake)[(size_t)b*(FD/4) + t] = f;
        float sq[6];
#pragma unroll
        for (int r = 0; r < NWAY; r++) {
            float4 v = sc4[r*(FD/4) + t];
            sq[r] = d4(v, v);
        }
        sq[5] = d4(f, f);
#pragma unroll
        for (int off = 16; off; off >>= 1)
#pragma unroll
            for (int r = 0; r < 6; r++)
                sq[r] += __shfl_xor_sync(0xffffffffu, sq[r], off);
        int lane = t & 31, w = t >> 5;
        if (lane == 0)
#pragma unroll
            for (int r = 0; r < 6; r++) sm[w*6 + r] = sq[r];
        __syncthreads();
        if (t < 6) {
            float s = 0.f;
            for (int w2 = 0; w2 < 8; w2++) s += sm[w2*6 + t];
            g_pinv[b*6 + t] = 1.f / sqrtf(s);
        }
        __syncthreads();
    }
    gsync(gen);

    // ============ S13: logits ============
    for (int u = blockIdx.x; u < BS*10; u += NBLK) {
        int b = u / 10, qc = u % 10;
        int w = t >> 5, lane = t & 31;
        int iq = qc*8 + w;
        if (iq < NQ) {
            const float4* q4  = (const float4*)qf     + ((size_t)b*NQ + iq)*(FD/4);
            const float4* sc4 = (const float4*)sc     + (size_t)b*NWAY*(FD/4);
            const float4* f4  = (const float4*)g_fake + (size_t)b*(FD/4);
            float qq = 0.f, d[6] = {0,0,0,0,0,0};
            for (int i = lane; i < FD/4; i += 32) {
                float4 x = q4[i];
                qq += d4(x, x);
#pragma unroll
                for (int r = 0; r < NWAY; r++) d[r] += d4(x, sc4[r*(FD/4) + i]);
                d[5] += d4(x, f4[i]);
            }
#pragma unroll
            for (int off = 16; off; off >>= 1) {
                qq += __shfl_xor_sync(0xffffffffu, qq, off);
#pragma unroll
                for (int r = 0; r < 6; r++) d[r] += __shfl_xor_sync(0xffffffffu, d[r], off);
            }
            if (lane == 0) {
                float s = temp[0] / sqrtf(qq);
                float* o = outL + ((size_t)b*NQ + iq)*6;
#pragma unroll
                for (int r = 0; r < 6; r++) o[r] = d[r] * s * g_pinv[b*6 + r];
            }
        }
    }
}

// ---------------- host ----------------
extern "C" void kernel_launch(void* const* d_in, const int* in_sizes, int n_in,
                              void* d_out, int out_size)
{
    const float* sc   = (const float*)d_in[0];
    const float* bw   = (const float*)d_in[1];
    const float* ss   = (const float*)d_in[2];
    const float* bsm  = (const float*)d_in[3];
    const float* qf   = (const float*)d_in[4];
    const float* Wm1  = (const float*)d_in[5];
    const float* bm1  = (const float*)d_in[6];
    const float* Wm2  = (const float*)d_in[7];
    const float* bm2  = (const float*)d_in[8];
    const float* Wvis = (const float*)d_in[9];
    const float* bvis = (const float*)d_in[10];
    const float* Wsem = (const float*)d_in[11];
    const float* bsem = (const float*)d_in[12];
    const float* Wq   = (const float*)d_in[13];
    const float* Wk   = (const float*)d_in[14];
    const float* Wv   = (const float*)d_in[15];
    const float* Wqs  = (const float*)d_in[16];
    const float* Wks  = (const float*)d_in[17];
    const float* Wfc  = (const float*)d_in[18];
    const float* temp = (const float*)d_in[19];
    float* out = (float*)d_out;

    int dev = 0;
    cudaGetDevice(&dev);
    int nsm = 148;
    cudaDeviceGetAttribute(&nsm, cudaDevAttrMultiProcessorCount, dev);
    int bpm = 1;
    cudaOccupancyMaxActiveBlocksPerMultiprocessor(&bpm, fused_k, 256, 0);
    if (bpm < 1) bpm = 1;
    int nblk = nsm * bpm;

    void* barp = nullptr;
    cudaGetSymbolAddress(&barp, g_barrier);
    cudaMemsetAsync(barp, 0, sizeof(unsigned int), 0);

    fused_k<<<nblk, 256>>>(sc, bw, ss, bsm, qf, Wm1, bm1, Wm2, bm2,
                           Wvis, bvis, Wsem, bsem, Wq, Wk, Wv, Wqs, Wks, Wfc,
                           temp, out);
}

// round 4
// speedup vs baseline: 1.4242x; 1.4242x over previous
#include <cuda_runtime.h>
#include <math.h>

#define FD    1024
#define SEM   300
#define NWAY  5
#define BS    32
#define NB    512
#define NQ    75
#define BTOT  (BS*NWAY)     // 160
#define CATD  (FD+SEM)      // 1324

#define MNq   (BTOT*FD)     // 163840
#define MNk   (BTOT*CATD)   // 211840
#define MNg   (BS*CATD)     // 42368

// ---------------- scratch ----------------
__device__ __align__(16) float g_scal[BTOT*SEM];
__device__ __align__(16) float g_avg [BS*CATD];
__device__ __align__(16) float g_gv  [BS*FD];
__device__ __align__(16) float g_gs  [BS*SEM];
__device__ __align__(16) float g_q   [BTOT*FD];
__device__ __align__(16) float g_qkg [BTOT*FD];
__device__ __align__(16) float g_qksg[BTOT*SEM];
__device__ __align__(16) float g_scr [BTOT*NB];
__device__ __align__(16) float g_mix [BTOT*FD];
__device__ __align__(16) float g_part [16*MNq];   // split-K partial slabs
__device__ __align__(16) float g_part2[14*MNg];   // gates partials
__device__ unsigned int g_barrier;

// ---------------- software grid barrier ----------------
__device__ __forceinline__ void gsync(int &gen)
{
    __syncthreads();
    if (threadIdx.x == 0) {
        __threadfence();
        atomicAdd(&g_barrier, 1u);
        unsigned target = (unsigned)gridDim.x * (unsigned)gen;
        unsigned v;
        do {
            asm volatile("ld.acquire.gpu.u32 %0, [%1];" : "=r"(v) : "l"(&g_barrier) : "memory");
            if (v >= target) break;
            __nanosleep(32);
        } while (true);
    }
    __syncthreads();
    gen++;
}

__device__ __forceinline__ float d4(float4 a, float4 b)
{ return a.x*b.x + a.y*b.y + a.z*b.z + a.w*b.w; }

// ---------------- tiled 32x128 GEMM partial ----------------
// part[slab + m*N + n] = A[m, ktile range] @ B
// BTR=false: B row-major [K,N], N-concat (B1 width N1 ld ldb1 | B2 ld ldb2)
// BTR=true : B row-major [N,K] (row n<N1 -> B1 ld ldb1, else B2 ld ldb2)
// REDA: A(m,k) = sum_z A[z*MNa + m*lda + k]  (Zred slabs)
template<bool BTR, bool REDA>
__device__ __forceinline__ void gemm_tile(
    const float* __restrict__ A, int M, int K, int lda, int Zred, size_t MNa,
    const float* __restrict__ B1, const float* __restrict__ B2,
    int N1, int N, int ldb1, int ldb2,
    float* __restrict__ part, size_t slab,
    int m0, int n0, int kt0, int kt1,
    float* __restrict__ As, float* __restrict__ Bs)
{
    const int t  = threadIdx.x;
    const int tx = t & 31, ty = t >> 5;
    float acc[4][4];
#pragma unroll
    for (int i=0;i<4;i++)
#pragma unroll
        for (int j=0;j<4;j++) acc[i][j]=0.f;

    for (int kt = kt0; kt < kt1; kt++) {
        int k0 = kt*32;
        // ---- A tile: As[kk][mm] (transposed), stride 36 ----
        {
            int mm = t >> 3, kq = t & 7;
            int mg = m0 + mm;
            float4 v = make_float4(0,0,0,0);
            int kg = k0 + kq*4;
            if (mg < M) {
                if (kg + 3 < K) {
                    if (!REDA) v = *(const float4*)&A[(size_t)mg*lda + kg];
                    else {
                        const float* base = A + (size_t)mg*lda + kg;
                        for (int z=0; z<Zred; z++) {
                            float4 w = *(const float4*)(base + (size_t)z*MNa);
                            v.x+=w.x; v.y+=w.y; v.z+=w.z; v.w+=w.w;
                        }
                    }
                } else {
                    float tmp[4]={0,0,0,0};
                    for (int j=0;j<4;j++){ int k2=kg+j; if (k2<K) tmp[j]=A[(size_t)mg*lda+k2]; }
                    v = make_float4(tmp[0],tmp[1],tmp[2],tmp[3]);
                }
            }
            As[(kq*4+0)*36 + mm] = v.x;
            As[(kq*4+1)*36 + mm] = v.y;
            As[(kq*4+2)*36 + mm] = v.z;
            As[(kq*4+3)*36 + mm] = v.w;
        }
        // ---- B tile: Bs[kk][nn], stride 132 ----
        if (!BTR) {
            int kk = t >> 3, q0 = t & 7;
            int kg = k0 + kk;
#pragma unroll
            for (int jj=0;jj<4;jj++) {
                int nn = (q0 + 8*jj)*4;
                int ng = n0 + nn;
                float4 v = make_float4(0,0,0,0);
                if (kg < K && ng < N) {
                    if (ng < N1) v = *(const float4*)&B1[(size_t)kg*ldb1 + ng];
                    else         v = *(const float4*)&B2[(size_t)kg*ldb2 + (ng-N1)];
                }
                *(float4*)&Bs[kk*132 + nn] = v;
            }
        } else {
            int kq = t & 7, nb = t >> 3;
#pragma unroll
            for (int r=0;r<4;r++) {
                int nn = nb*4 + r;
                int ng = n0 + nn;
                float4 v = make_float4(0,0,0,0);
                if (ng < N) {
                    const float* brow = (ng < N1) ? &B1[(size_t)ng*ldb1]
                                                  : &B2[(size_t)(ng-N1)*ldb2];
                    int kg = k0 + kq*4;
                    if (kg + 3 < K) v = *(const float4*)&brow[kg];
                    else {
                        float tmp[4]={0,0,0,0};
                        for (int j=0;j<4;j++){ int k2=kg+j; if (k2<K) tmp[j]=brow[k2]; }
                        v = make_float4(tmp[0],tmp[1],tmp[2],tmp[3]);
                    }
                }
                Bs[(kq*4+0)*132 + nn] = v.x;
                Bs[(kq*4+1)*132 + nn] = v.y;
                Bs[(kq*4+2)*132 + nn] = v.z;
                Bs[(kq*4+3)*132 + nn] = v.w;
            }
        }
        __syncthreads();
#pragma unroll
        for (int kk=0; kk<32; kk++) {
            float4 a = *(const float4*)&As[kk*36 + ty*4];
            float4 b = *(const float4*)&Bs[kk*132 + tx*4];
            acc[0][0]=fmaf(a.x,b.x,acc[0][0]); acc[0][1]=fmaf(a.x,b.y,acc[0][1]);
            acc[0][2]=fmaf(a.x,b.z,acc[0][2]); acc[0][3]=fmaf(a.x,b.w,acc[0][3]);
            acc[1][0]=fmaf(a.y,b.x,acc[1][0]); acc[1][1]=fmaf(a.y,b.y,acc[1][1]);
            acc[1][2]=fmaf(a.y,b.z,acc[1][2]); acc[1][3]=fmaf(a.y,b.w,acc[1][3]);
            acc[2][0]=fmaf(a.z,b.x,acc[2][0]); acc[2][1]=fmaf(a.z,b.y,acc[2][1]);
            acc[2][2]=fmaf(a.z,b.z,acc[2][2]); acc[2][3]=fmaf(a.z,b.w,acc[2][3]);
            acc[3][0]=fmaf(a.w,b.x,acc[3][0]); acc[3][1]=fmaf(a.w,b.y,acc[3][1]);
            acc[3][2]=fmaf(a.w,b.z,acc[3][2]); acc[3][3]=fmaf(a.w,b.w,acc[3][3]);
        }
        __syncthreads();
    }
#pragma unroll
    for (int i=0;i<4;i++) {
        int mg = m0 + ty*4 + i;
        int ng = n0 + tx*4;
        if (mg < M && ng < N)
            *(float4*)&part[slab + (size_t)mg*N + ng] =
                make_float4(acc[i][0],acc[i][1],acc[i][2],acc[i][3]);
    }
}

// stage unit counts
#define U_MLP   40
#define U_QP1   320
#define U_AVG   166
#define S0U     (U_MLP+U_QP1+U_AVG)      // 526
#define U_QP2   200
#define U_GAT   154
#define S1U     (U_QP2+U_GAT)            // 354
#define U_QR    640
#define U_GR    166
#define S2U     (U_QR+U_GR)              // 806

__global__ void __launch_bounds__(256, 2) fused_k(
    const float* __restrict__ sc,  const float* __restrict__ bw,
    const float* __restrict__ ss,  const float* __restrict__ bsm,
    const float* __restrict__ qf,
    const float* __restrict__ Wm1, const float* __restrict__ bm1,
    const float* __restrict__ Wm2, const float* __restrict__ bm2,
    const float* __restrict__ Wvis,const float* __restrict__ bvis,
    const float* __restrict__ Wsem,const float* __restrict__ bsem,
    const float* __restrict__ Wq,  const float* __restrict__ Wk,
    const float* __restrict__ Wv,  const float* __restrict__ Wqs,
    const float* __restrict__ Wks, const float* __restrict__ Wfc,
    const float* __restrict__ temp, float* __restrict__ outL)
{
    __shared__ __align__(16) float sm[5376];
    float* As = sm;          // 32*36 = 1152
    float* Bs = sm + 1152;   // 32*132 = 4224
    const int NBLK = gridDim.x;
    const int t = threadIdx.x;
    int gen = 1;

    // ===== S0: MLP | qp1 (sc@Wq) | avg =====
    for (int u = blockIdx.x; u < S0U; u += NBLK) {
        if (u < U_MLP) {
            int m0u = u * 4;
            for (int i = t; i < 4*SEM; i += 256)
                sm[i] = ss[(size_t)(m0u + i/SEM)*SEM + (i % SEM)];
            __syncthreads();
            for (int n = t; n < SEM; n += 256) {
                float a0 = bm1[n], a1 = a0, a2 = a0, a3 = a0;
                for (int k = 0; k < SEM; k++) {
                    float w = Wm1[(size_t)k*SEM + n];
                    a0 = fmaf(sm[0*SEM+k], w, a0); a1 = fmaf(sm[1*SEM+k], w, a1);
                    a2 = fmaf(sm[2*SEM+k], w, a2); a3 = fmaf(sm[3*SEM+k], w, a3);
                }
                sm[4*SEM + 0*SEM + n] = (a0 >= 0.f) ? a0 : 0.1f*a0;
                sm[4*SEM + 1*SEM + n] = (a1 >= 0.f) ? a1 : 0.1f*a1;
                sm[4*SEM + 2*SEM + n] = (a2 >= 0.f) ? a2 : 0.1f*a2;
                sm[4*SEM + 3*SEM + n] = (a3 >= 0.f) ? a3 : 0.1f*a3;
            }
            __syncthreads();
            for (int n = t; n < SEM; n += 256) {
                float a0 = bm2[n], a1 = a0, a2 = a0, a3 = a0;
                for (int k = 0; k < SEM; k++) {
                    float w = Wm2[(size_t)k*SEM + n];
                    a0 = fmaf(sm[4*SEM+0*SEM+k], w, a0); a1 = fmaf(sm[4*SEM+1*SEM+k], w, a1);
                    a2 = fmaf(sm[4*SEM+2*SEM+k], w, a2); a3 = fmaf(sm[4*SEM+3*SEM+k], w, a3);
                }
                g_scal[(size_t)(m0u+0)*SEM + n] = a0;
                g_scal[(size_t)(m0u+1)*SEM + n] = a1;
                g_scal[(size_t)(m0u+2)*SEM + n] = a2;
                g_scal[(size_t)(m0u+3)*SEM + n] = a3;
            }
            __syncthreads();
        } else if (u < U_MLP + U_QP1) {
            int uu = u - U_MLP;
            int z = uu & 7, r = uu >> 3;
            int nt = r & 7, mt = r >> 3;
            gemm_tile<false,false>(sc, BTOT, FD, FD, 0, 0,
                Wq, Wq, FD, FD, FD, FD,
                g_part, (size_t)z*MNq, mt*32, nt*128, z*4, z*4+4, As, Bs);
        } else {
            int i = (u - (U_MLP+U_QP1))*256 + t;
            if (i < BS*CATD) {
                int b = i / CATD, c = i % CATD;
                float s = 0.f;
                if (c < FD) {
                    const float* p = bw + (size_t)b*NB*FD + c;
#pragma unroll 8
                    for (int n = 0; n < NB; n++) s += p[(size_t)n*FD];
                } else {
                    const float* p = bsm + (size_t)b*NB*SEM + (c - FD);
#pragma unroll 8
                    for (int n = 0; n < NB; n++) s += p[(size_t)n*SEM];
                }
                g_avg[b*CATD + c] = s * (1.f/NB);
            }
        }
    }
    gsync(gen);

    // ===== S1: qp2 (s@Wqs) | gates partials =====
    for (int u = blockIdx.x; u < S1U; u += NBLK) {
        if (u < U_QP2) {
            int z = u % 5, r = u / 5;
            int nt = r & 7, mt = r >> 3;
            gemm_tile<false,false>(g_scal, BTOT, SEM, SEM, 0, 0,
                Wqs, Wqs, FD, FD, FD, FD,
                g_part, (size_t)(8+z)*MNq, mt*32, nt*128, z*2, z*2+2, As, Bs);
        } else {
            int uu = u - U_QP2;
            int z = uu % 14, nt = uu / 14;
            gemm_tile<false,false>(g_avg, BS, CATD, CATD, 0, 0,
                Wvis, Wsem, FD, CATD, FD, SEM,
                g_part2, (size_t)z*MNg, 0, nt*128, z*3, z*3+3, As, Bs);
        }
    }
    gsync(gen);

    // ===== S2: q reduce | gates reduce =====
    for (int u = blockIdx.x; u < S2U; u += NBLK) {
        if (u < U_QR) {
            size_t i = (size_t)u*256 + t;
            float v = 0.f;
            for (int z = 0; z < 13; z++) v += g_part[(size_t)z*MNq + i];
            g_q[i] = v;
        } else {
            size_t i = (size_t)(u - U_QR)*256 + t;
            if (i < (size_t)BS*CATD) {
                int m = (int)(i / CATD), n = (int)(i % CATD);
                float v = 0.f;
                for (int z = 0; z < 14; z++) v += g_part2[(size_t)z*MNg + i];
                if (n < FD) {
                    v += bvis[n];
                    g_gv[(size_t)m*FD + n] = 1.f + 1.f/(1.f + __expf(-v));
                } else {
                    v += bsem[n - FD];
                    g_gs[(size_t)m*SEM + (n - FD)] = 1.f + 1.f/(1.f + __expf(-v));
                }
            }
        }
    }
    gsync(gen);

    // ===== S3: qk partials (q @ [Wk;Wks]^T, B transposed-load) =====
    for (int u = blockIdx.x; u < 440; u += NBLK) {
        int z = u & 7, r = u >> 3;
        int nt = r % 11, mt = r / 11;
        gemm_tile<true,false>(g_q, BTOT, FD, FD, 0, 0,
            Wk, Wks, FD, CATD, FD, FD,
            g_part, (size_t)z*MNk, mt*32, nt*128, z*4, z*4+4, As, Bs);
    }
    gsync(gen);

    // ===== S4: qk reduce * gates =====
    for (int u = blockIdx.x; u < 828; u += NBLK) {
        size_t i = (size_t)u*256 + t;
        if (i < (size_t)MNk) {
            int m = (int)(i / CATD), n = (int)(i % CATD);
            float v = 0.f;
            for (int z = 0; z < 8; z++) v += g_part[(size_t)z*MNk + i];
            int b = m / NWAY;
            if (n < FD) g_qkg [(size_t)m*FD  + n]      = v * g_gv[(size_t)b*FD  + n];
            else        g_qksg[(size_t)m*SEM + (n-FD)] = v * g_gs[(size_t)b*SEM + (n-FD)];
        }
    }
    gsync(gen);

    // ===== S5: scores =====
    for (int u = blockIdx.x; u < 512; u += NBLK) {
        int b = u / 16, ch = u % 16;
        int w = t >> 5, lane = t & 31;
        int nbase = ch*32 + w*4;
        float acc[4][5];
#pragma unroll
        for (int j = 0; j < 4; j++)
#pragma unroll
            for (int p = 0; p < 5; p++) acc[j][p] = 0.f;
        const float4* qkg4 = (const float4*)g_qkg  + (size_t)b*NWAY*(FD/4);
        const float4* qks4 = (const float4*)g_qksg + (size_t)b*NWAY*(SEM/4);
        const float4* bw4  = (const float4*)bw     + (size_t)b*NB*(FD/4);
        const float4* bs4  = (const float4*)bsm    + (size_t)b*NB*(SEM/4);
#pragma unroll
        for (int tt = 0; tt < 8; tt++) {
            int c = tt*32 + lane;
            float4 qv[5];
#pragma unroll
            for (int p = 0; p < 5; p++) qv[p] = qkg4[p*(FD/4) + c];
#pragma unroll
            for (int j = 0; j < 4; j++) {
                float4 x = bw4[(size_t)(nbase+j)*(FD/4) + c];
#pragma unroll
                for (int p = 0; p < 5; p++) acc[j][p] += d4(x, qv[p]);
            }
        }
#pragma unroll
        for (int tt = 0; tt < 3; tt++) {
            int c = tt*32 + lane;
            bool ok = c < (SEM/4);
            float4 qv[5];
#pragma unroll
            for (int p = 0; p < 5; p++)
                qv[p] = ok ? qks4[p*(SEM/4) + c] : make_float4(0,0,0,0);
#pragma unroll
            for (int j = 0; j < 4; j++) {
                float4 x = ok ? bs4[(size_t)(nbase+j)*(SEM/4) + c] : make_float4(0,0,0,0);
#pragma unroll
                for (int p = 0; p < 5; p++) acc[j][p] += d4(x, qv[p]);
            }
        }
#pragma unroll
        for (int off = 16; off; off >>= 1)
#pragma unroll
            for (int j = 0; j < 4; j++)
#pragma unroll
                for (int p = 0; p < 5; p++)
                    acc[j][p] += __shfl_xor_sync(0xffffffffu, acc[j][p], off);
#pragma unroll
        for (int j = 0; j < 4; j++)
            if (lane == j) {
                int n = nbase + j;
#pragma unroll
                for (int p = 0; p < 5; p++)
                    g_scr[(size_t)(b*NWAY+p)*NB + n] = acc[j][p] * (1.f/32.f);
            }
    }
    gsync(gen);

    // ===== S6: softmax over 512 =====
    for (int u = blockIdx.x; u < BTOT; u += NBLK) {
        float v0 = g_scr[(size_t)u*NB + t], v1 = g_scr[(size_t)u*NB + 256 + t];
        sm[t] = fmaxf(v0, v1); __syncthreads();
        for (int s = 128; s; s >>= 1) { if (t < s) sm[t] = fmaxf(sm[t], sm[t+s]); __syncthreads(); }
        float mx = sm[0]; __syncthreads();
        float e0 = __expf(v0 - mx), e1 = __expf(v1 - mx);
        sm[t] = e0 + e1; __syncthreads();
        for (int s = 128; s; s >>= 1) { if (t < s) sm[t] += sm[t+s]; __syncthreads(); }
        float inv = 1.f / sm[0]; __syncthreads();
        g_scr[(size_t)u*NB + t] = e0*inv;
        g_scr[(size_t)u*NB + 256 + t] = e1*inv;
    }
    gsync(gen);

    // ===== S7: mix =====
    for (int u = blockIdx.x; u < 128; u += NBLK) {
        int b = u / 4, fc = u % 4;
        for (int i = t; i < NWAY*NB; i += 256)
            sm[i] = g_scr[(size_t)b*NWAY*NB + i];
        __syncthreads();
        int f = fc*256 + t;
        float a0=0,a1=0,a2=0,a3=0,a4=0;
        const float* p = bw + (size_t)b*NB*FD + f;
#pragma unroll 8
        for (int n = 0; n < NB; n++) {
            float x = p[(size_t)n*FD];
            a0 = fmaf(x, sm[0*NB+n], a0); a1 = fmaf(x, sm[1*NB+n], a1);
            a2 = fmaf(x, sm[2*NB+n], a2); a3 = fmaf(x, sm[3*NB+n], a3);
            a4 = fmaf(x, sm[4*NB+n], a4);
        }
        float g = g_gv[(size_t)b*FD + f];
        g_mix[(size_t)(b*NWAY+0)*FD + f] = a0*g;
        g_mix[(size_t)(b*NWAY+1)*FD + f] = a1*g;
        g_mix[(size_t)(b*NWAY+2)*FD + f] = a2*g;
        g_mix[(size_t)(b*NWAY+3)*FD + f] = a3*g;
        g_mix[(size_t)(b*NWAY+4)*FD + f] = a4*g;
        __syncthreads();
    }
    gsync(gen);

    // ===== S8: outv partials (mix@Wv), slots 0..7 =====
    for (int u = blockIdx.x; u < 320; u += NBLK) {
        int z = u & 7, r = u >> 3;
        int nt = r & 7, mt = r >> 3;
        gemm_tile<false,false>(g_mix, BTOT, FD, FD, 0, 0,
            Wv, Wv, FD, FD, FD, FD,
            g_part, (size_t)z*MNq, mt*32, nt*128, z*4, z*4+4, As, Bs);
    }
    gsync(gen);

    // ===== S9: out partials (reduce(outv)@Wfc), slots 8..15, inline A-reduce =====
    for (int u = blockIdx.x; u < 320; u += NBLK) {
        int z = u & 7, r = u >> 3;
        int nt = r & 7, mt = r >> 3;
        gemm_tile<false,true>(g_part, BTOT, FD, FD, 8, (size_t)MNq,
            Wfc, Wfc, FD, FD, FD, FD,
            g_part, (size_t)(8+z)*MNq, mt*32, nt*128, z*4, z*4+4, As, Bs);
    }
    gsync(gen);

    // ===== S10: fused out-reduce + residual + fake + norms + logits =====
    for (int u = blockIdx.x; u < BS*10; u += NBLK) {
        int b = u / 10, qc = u % 10;
        // fake + prototype norms into sm (fake at [0..1023], red at [1024..], pinv [1072..])
        {
            const float4* sc4 = (const float4*)sc + (size_t)b*NWAY*(FD/4);
            float4 f = make_float4(0,0,0,0);
            float sq[6];
#pragma unroll
            for (int c = 0; c < NWAY; c++) {
                size_t row = (size_t)(b*NWAY + c)*FD;
                float4 o = sc4[c*(FD/4) + t];
                sq[c] = d4(o, o);
                for (int z = 8; z < 16; z++) {
                    float4 w = *(const float4*)&g_part[(size_t)z*MNq + row + t*4];
                    o.x+=w.x; o.y+=w.y; o.z+=w.z; o.w+=w.w;
                }
                f.x+=o.x; f.y+=o.y; f.z+=o.z; f.w+=o.w;
            }
            f.x*=0.2f; f.y*=0.2f; f.z*=0.2f; f.w*=0.2f;
            ((float4*)sm)[t] = f;
            sq[5] = d4(f, f);
#pragma unroll
            for (int off = 16; off; off >>= 1)
#pragma unroll
                for (int r = 0; r < 6; r++)
                    sq[r] += __shfl_xor_sync(0xffffffffu, sq[r], off);
            int lane = t & 31, w = t >> 5;
            if (lane == 0)
#pragma unroll
                for (int r = 0; r < 6; r++) sm[1024 + w*6 + r] = sq[r];
            __syncthreads();
            if (t < 6) {
                float s = 0.f;
                for (int w2 = 0; w2 < 8; w2++) s += sm[1024 + w2*6 + t];
                sm[1072 + t] = 1.f / sqrtf(s);
            }
            __syncthreads();
        }
        // logits for 8 queries
        {
            int w = t >> 5, lane = t & 31;
            int iq = qc*8 + w;
            if (iq < NQ) {
                const float4* q4  = (const float4*)qf + ((size_t)b*NQ + iq)*(FD/4);
                const float4* sc4 = (const float4*)sc + (size_t)b*NWAY*(FD/4);
                const float4* f4  = (const float4*)sm;
                float qq = 0.f, d[6] = {0,0,0,0,0,0};
                for (int i = lane; i < FD/4; i += 32) {
                    float4 x = q4[i];
                    qq += d4(x, x);
#pragma unroll
                    for (int r = 0; r < NWAY; r++) d[r] += d4(x, sc4[r*(FD/4) + i]);
                    d[5] += d4(x, f4[i]);
                }
#pragma unroll
                for (int off = 16; off; off >>= 1) {
                    qq += __shfl_xor_sync(0xffffffffu, qq, off);
#pragma unroll
                    for (int r = 0; r < 6; r++) d[r] += __shfl_xor_sync(0xffffffffu, d[r], off);
                }
                if (lane == 0) {
                    float s = temp[0] / sqrtf(qq);
                    float* o = outL + ((size_t)b*NQ + iq)*6;
#pragma unroll
                    for (int r = 0; r < 6; r++) o[r] = d[r] * s * sm[1072 + r];
                }
            }
        }
        __syncthreads();
    }
}

// ---------------- host ----------------
extern "C" void kernel_launch(void* const* d_in, const int* in_sizes, int n_in,
                              void* d_out, int out_size)
{
    const float* sc   = (const float*)d_in[0];
    const float* bw   = (const float*)d_in[1];
    const float* ss   = (const float*)d_in[2];
    const float* bsm  = (const float*)d_in[3];
    const float* qf   = (const float*)d_in[4];
    const float* Wm1  = (const float*)d_in[5];
    const float* bm1  = (const float*)d_in[6];
    const float* Wm2  = (const float*)d_in[7];
    const float* bm2  = (const float*)d_in[8];
    const float* Wvis = (const float*)d_in[9];
    const float* bvis = (const float*)d_in[10];
    const float* Wsem = (const float*)d_in[11];
    const float* bsem = (const float*)d_in[12];
    const float* Wq   = (const float*)d_in[13];
    const float* Wk   = (const float*)d_in[14];
    const float* Wv   = (const float*)d_in[15];
    const float* Wqs  = (const float*)d_in[16];
    const float* Wks  = (const float*)d_in[17];
    const float* Wfc  = (const float*)d_in[18];
    const float* temp = (const float*)d_in[19];
    float* out = (float*)d_out;

    int dev = 0;
    cudaGetDevice(&dev);
    int nsm = 148;
    cudaDeviceGetAttribute(&nsm, cudaDevAttrMultiProcessorCount, dev);
    int bpm = 1;
    cudaOccupancyMaxActiveBlocksPerMultiprocessor(&bpm, fused_k, 256, 0);
    if (bpm < 1) bpm = 1;
    int nblk = nsm * bpm;

    void* barp = nullptr;
    cudaGetSymbolAddress(&barp, g_barrier);
    cudaMemsetAsync(barp, 0, sizeof(unsigned int), 0);

    fused_k<<<nblk, 256>>>(sc, bw, ss, bsm, qf, Wm1, bm1, Wm2, bm2,
                           Wvis, bvis, Wsem, bsem, Wq, Wk, Wv, Wqs, Wks, Wfc,
                           temp, out);
}

// round 5
// speedup vs baseline: 1.7661x; 1.2400x over previous
#include <cuda_runtime.h>
#include <mma.h>
#include <math.h>

using namespace nvcuda;

#define FD    1024
#define SEM   300
#define NWAY  5
#define BS    32
#define NB    512
#define NQ    75
#define BTOT  (BS*NWAY)     // 160
#define CATD  (FD+SEM)      // 1324

#define MNq   (BTOT*FD)     // 163840
#define MNk   (BTOT*CATD)   // 211840
#define SLABK (BTOT*1408)   // 225280 (padded qk partial slab)
#define SLABG (BS*1408)     // 45056
#define SLABF (BS*FD)       // 32768

// ---------------- scratch ----------------
__device__ __align__(32) float g_scal[BTOT*SEM];
__device__ __align__(32) float g_gv  [BS*FD];
__device__ __align__(32) float g_gs  [BS*SEM];
__device__ __align__(32) float g_q   [BTOT*FD];
__device__ __align__(32) float g_qkg [BTOT*FD];
__device__ __align__(32) float g_qksg[BTOT*SEM];
__device__ __align__(32) float g_scr [BTOT*NB];
__device__ __align__(32) float g_avgp[4*BS*CATD];
__device__ __align__(32) float g_mixp[4*SLABF];
__device__ __align__(32) float g_part [16*MNq];
__device__ __align__(32) float g_part2[14*SLABG];
__device__ unsigned int g_barrier;

// ---------------- software grid barrier ----------------
__device__ __forceinline__ void gsync(int &gen)
{
    __syncthreads();
    if (threadIdx.x == 0) {
        __threadfence();
        atomicAdd(&g_barrier, 1u);
        unsigned target = (unsigned)gridDim.x * (unsigned)gen;
        unsigned v;
        do {
            asm volatile("ld.acquire.gpu.u32 %0, [%1];" : "=r"(v) : "l"(&g_barrier) : "memory");
            if (v >= target) break;
            __nanosleep(32);
        } while (true);
    }
    __syncthreads();
    gen++;
}

__device__ __forceinline__ float d4(float4 a, float4 b)
{ return a.x*b.x + a.y*b.y + a.z*b.z + a.w*b.w; }

// ---------------- wmma tf32x2-split GEMM tile (32m x 128n per block) ----------------
// part[slab + m*ldp + n] = A' @ B   (fp32-equivalent accuracy via hi/lo split, 3 mma)
// A'(m,k) = (REDA ? sum_z A[z*slabA + m*lda + k] : A[m*lda+k]) * ascale * (GATEA ? gate[(m/gdiv)*lda+k] : 1)
// BTR=false: B row-major [K,N], N-concat B1(width N1)|B2 ; BTR=true: B row-major [N,K], row-concat.
typedef wmma::fragment<wmma::matrix_a, 16,16,8, wmma::precision::tf32, wmma::row_major> FragA;
typedef wmma::fragment<wmma::matrix_b, 16,16,8, wmma::precision::tf32, wmma::row_major> FragBR;
typedef wmma::fragment<wmma::matrix_b, 16,16,8, wmma::precision::tf32, wmma::col_major> FragBC;
typedef wmma::fragment<wmma::accumulator, 16,16,8, float> FragC;

template<class F>
__device__ __forceinline__ void split_frag(F& hi, F& lo)
{
#pragma unroll
    for (int i = 0; i < hi.num_elements; i++) {
        float r = hi.x[i];
        float h = wmma::__float_to_tf32(r);
        hi.x[i] = h;
        lo.x[i] = wmma::__float_to_tf32(r - h);
    }
}

template<bool BTR, bool REDA, bool GATEA>
__device__ __forceinline__ void gemm_w(
    const float* __restrict__ A, int M, int K, int lda,
    int Zred, size_t slabA, float ascale, const float* __restrict__ gateA, int gdiv,
    const float* __restrict__ B1, const float* __restrict__ B2,
    int N1, int N, int ldb1, int ldb2,
    float* __restrict__ part, size_t slab, int ldp,
    int m0, int n0, int kt0, int kt1,
    float* __restrict__ As, float* __restrict__ Bs)
{
    const int t = threadIdx.x;
    const int warp = t >> 5;
    const int mrow = warp >> 2;         // 0..1
    const int nq   = warp & 3;          // 0..3
    FragC c0, c1;
    wmma::fill_fragment(c0, 0.f);
    wmma::fill_fragment(c1, 0.f);

    for (int kt = kt0; kt < kt1; kt++) {
        int k0 = kt*32;
        // ---- A tile As[m][k], stride 40 ----
        {
            int mm = t >> 3, kq = (t & 7)*4;
            int mg = m0 + mm, kg = k0 + kq;
            float vv[4] = {0,0,0,0};
            if (mg < M && kg < K) {
                if (kg + 3 < K) {
                    float4 v;
                    if (REDA) {
                        v = make_float4(0,0,0,0);
                        for (int z = 0; z < Zred; z++) {
                            float4 w = *(const float4*)&A[(size_t)z*slabA + (size_t)mg*lda + kg];
                            v.x+=w.x; v.y+=w.y; v.z+=w.z; v.w+=w.w;
                        }
                    } else v = *(const float4*)&A[(size_t)mg*lda + kg];
                    v.x*=ascale; v.y*=ascale; v.z*=ascale; v.w*=ascale;
                    if (GATEA) {
                        float4 g = *(const float4*)&gateA[(size_t)(mg/gdiv)*lda + kg];
                        v.x*=g.x; v.y*=g.y; v.z*=g.z; v.w*=g.w;
                    }
                    vv[0]=v.x; vv[1]=v.y; vv[2]=v.z; vv[3]=v.w;
                } else {
                    for (int j = 0; j < 4; j++) {
                        int k2 = kg + j;
                        if (k2 < K) {
                            float s = 0.f;
                            if (REDA) { for (int z=0; z<Zred; z++) s += A[(size_t)z*slabA + (size_t)mg*lda + k2]; }
                            else s = A[(size_t)mg*lda + k2];
                            s *= ascale;
                            if (GATEA) s *= gateA[(size_t)(mg/gdiv)*lda + k2];
                            vv[j] = s;
                        }
                    }
                }
            }
            *(float4*)&As[mm*40 + kq] = make_float4(vv[0],vv[1],vv[2],vv[3]);
        }
        // ---- B tile ----
        if (!BTR) {
            int kk = t >> 3, q0 = t & 7;
            int kg = k0 + kk;
#pragma unroll
            for (int jj = 0; jj < 4; jj++) {
                int n = (q0 + 8*jj)*4;
                int ng = n0 + n;
                float4 v = make_float4(0,0,0,0);
                if (kg < K && ng < N) {
                    if (ng < N1) v = *(const float4*)&B1[(size_t)kg*ldb1 + ng];
                    else         v = *(const float4*)&B2[(size_t)kg*ldb2 + (ng-N1)];
                }
                *(float4*)&Bs[kk*136 + n] = v;
            }
        } else {
            int n = t >> 1, k0w = (t & 1)*16;
            int ng = n0 + n;
            const float* brow = nullptr;
            if (ng < N) brow = (ng < N1) ? &B1[(size_t)ng*ldb1] : &B2[(size_t)(ng-N1)*ldb2];
#pragma unroll
            for (int jj = 0; jj < 4; jj++) {
                int kg = k0 + k0w + jj*4;
                float4 v = make_float4(0,0,0,0);
                if (brow) {
                    if (kg + 3 < K) v = *(const float4*)&brow[kg];
                    else {
                        float tmp[4] = {0,0,0,0};
                        for (int j=0;j<4;j++){ int k2=kg+j; if (k2<K) tmp[j]=brow[k2]; }
                        v = make_float4(tmp[0],tmp[1],tmp[2],tmp[3]);
                    }
                }
                *(float4*)&Bs[n*40 + k0w + jj*4] = v;
            }
        }
        __syncthreads();
#pragma unroll
        for (int kk = 0; kk < 32; kk += 8) {
            FragA ah, al;
            wmma::load_matrix_sync(ah, As + mrow*16*40 + kk, 40);
            split_frag(ah, al);
            if (!BTR) {
                FragBR b0h,b0l,b1h,b1l;
                wmma::load_matrix_sync(b0h, Bs + kk*136 + nq*32, 136);
                wmma::load_matrix_sync(b1h, Bs + kk*136 + nq*32 + 16, 136);
                split_frag(b0h, b0l); split_frag(b1h, b1l);
                wmma::mma_sync(c0, ah, b0h, c0);
                wmma::mma_sync(c0, ah, b0l, c0);
                wmma::mma_sync(c0, al, b0h, c0);
                wmma::mma_sync(c1, ah, b1h, c1);
                wmma::mma_sync(c1, ah, b1l, c1);
                wmma::mma_sync(c1, al, b1h, c1);
            } else {
                FragBC b0h,b0l,b1h,b1l;
                wmma::load_matrix_sync(b0h, Bs + (nq*32)*40 + kk, 40);
                wmma::load_matrix_sync(b1h, Bs + (nq*32+16)*40 + kk, 40);
                split_frag(b0h, b0l); split_frag(b1h, b1l);
                wmma::mma_sync(c0, ah, b0h, c0);
                wmma::mma_sync(c0, ah, b0l, c0);
                wmma::mma_sync(c0, al, b0h, c0);
                wmma::mma_sync(c1, ah, b1h, c1);
                wmma::mma_sync(c1, ah, b1l, c1);
                wmma::mma_sync(c1, al, b1h, c1);
            }
        }
        __syncthreads();
    }
    float* cb = part + slab + (size_t)(m0 + mrow*16)*ldp + n0 + nq*32;
    wmma::store_matrix_sync(cb,      c0, ldp, wmma::mem_row_major);
    wmma::store_matrix_sync(cb + 16, c1, ldp, wmma::mem_row_major);
}

// stage unit counts
#define U_MLP   40
#define U_QP1   320
#define U_AVG   256
#define S0U     (U_MLP+U_QP1+U_AVG)     // 616
#define U_QP2   200
#define U_GAT   154
#define S1U     (U_QP2+U_GAT)           // 354
#define U_QR    160
#define U_GR    166
#define S2U     (U_QR+U_GR)             // 326

__global__ void __launch_bounds__(256, 2) fused_k(
    const float* __restrict__ sc,  const float* __restrict__ bw,
    const float* __restrict__ ss,  const float* __restrict__ bsm,
    const float* __restrict__ qf,
    const float* __restrict__ Wm1, const float* __restrict__ bm1,
    const float* __restrict__ Wm2, const float* __restrict__ bm2,
    const float* __restrict__ Wvis,const float* __restrict__ bvis,
    const float* __restrict__ Wsem,const float* __restrict__ bsem,
    const float* __restrict__ Wq,  const float* __restrict__ Wk,
    const float* __restrict__ Wv,  const float* __restrict__ Wqs,
    const float* __restrict__ Wks, const float* __restrict__ Wfc,
    const float* __restrict__ temp, float* __restrict__ outL)
{
    __shared__ __align__(32) float sm[6400];
    float* As = sm;           // 32*40 = 1280
    float* Bs = sm + 1280;    // up to 128*40 = 5120
    const int NBLK = gridDim.x;
    const int t = threadIdx.x;
    int gen = 1;

    // ===== S0: MLP | qp1 (sc@Wq) | avg partials =====
    for (int u = blockIdx.x; u < S0U; u += NBLK) {
        if (u < U_MLP) {
            int m0u = u * 4;
            for (int i = t; i < 4*SEM; i += 256)
                sm[i] = ss[(size_t)(m0u + i/SEM)*SEM + (i % SEM)];
            __syncthreads();
            for (int n = t; n < SEM; n += 256) {
                float a0 = bm1[n], a1 = a0, a2 = a0, a3 = a0;
                for (int k = 0; k < SEM; k++) {
                    float w = Wm1[(size_t)k*SEM + n];
                    a0 = fmaf(sm[0*SEM+k], w, a0); a1 = fmaf(sm[1*SEM+k], w, a1);
                    a2 = fmaf(sm[2*SEM+k], w, a2); a3 = fmaf(sm[3*SEM+k], w, a3);
                }
                sm[1280 + 0*SEM + n] = (a0 >= 0.f) ? a0 : 0.1f*a0;
                sm[1280 + 1*SEM + n] = (a1 >= 0.f) ? a1 : 0.1f*a1;
                sm[1280 + 2*SEM + n] = (a2 >= 0.f) ? a2 : 0.1f*a2;
                sm[1280 + 3*SEM + n] = (a3 >= 0.f) ? a3 : 0.1f*a3;
            }
            __syncthreads();
            for (int n = t; n < SEM; n += 256) {
                float a0 = bm2[n], a1 = a0, a2 = a0, a3 = a0;
                for (int k = 0; k < SEM; k++) {
                    float w = Wm2[(size_t)k*SEM + n];
                    a0 = fmaf(sm[1280+0*SEM+k], w, a0); a1 = fmaf(sm[1280+1*SEM+k], w, a1);
                    a2 = fmaf(sm[1280+2*SEM+k], w, a2); a3 = fmaf(sm[1280+3*SEM+k], w, a3);
                }
                g_scal[(size_t)(m0u+0)*SEM + n] = a0;
                g_scal[(size_t)(m0u+1)*SEM + n] = a1;
                g_scal[(size_t)(m0u+2)*SEM + n] = a2;
                g_scal[(size_t)(m0u+3)*SEM + n] = a3;
            }
            __syncthreads();
        } else if (u < U_MLP + U_QP1) {
            int uu = u - U_MLP;
            int z = uu & 7, r = uu >> 3;
            int nt = r & 7, mt = r >> 3;
            gemm_w<false,false,false>(sc, BTOT, FD, FD, 0, 0, 1.f, nullptr, 1,
                Wq, Wq, FD, FD, FD, FD,
                g_part, (size_t)z*MNq, FD, mt*32, nt*128, z*4, z*4+4, As, Bs);
        } else {
            int uu = u - (U_MLP+U_QP1);
            int chunk = uu >> 6, r = uu & 63;
            int b = r >> 1, cpart = r & 1;
            int c4 = cpart*256 + t;
            if (c4 < CATD/4) {
                int c = c4*4;
                int n0 = chunk*128;
                float4 v = make_float4(0,0,0,0);
                if (c < FD) {
                    const float4* p = (const float4*)bw + ((size_t)b*NB + n0)*(FD/4) + c4;
#pragma unroll 8
                    for (int n = 0; n < 128; n++) {
                        float4 x = p[(size_t)n*(FD/4)];
                        v.x+=x.x; v.y+=x.y; v.z+=x.z; v.w+=x.w;
                    }
                } else {
                    const float4* p = (const float4*)(bsm + ((size_t)b*NB + n0)*SEM + (c-FD));
#pragma unroll 8
                    for (int n = 0; n < 128; n++) {
                        float4 x = p[(size_t)n*(SEM/4)];
                        v.x+=x.x; v.y+=x.y; v.z+=x.z; v.w+=x.w;
                    }
                }
                *(float4*)&g_avgp[(size_t)chunk*BS*CATD + (size_t)b*CATD + c] = v;
            }
        }
    }
    gsync(gen);

    // ===== S1: qp2 (s@Wqs) | gates (REDA avg, scaled 1/512) =====
    for (int u = blockIdx.x; u < S1U; u += NBLK) {
        if (u < U_QP2) {
            int z = u % 5, r = u / 5;
            int nt = r & 7, mt = r >> 3;
            gemm_w<false,false,false>(g_scal, BTOT, SEM, SEM, 0, 0, 1.f, nullptr, 1,
                Wqs, Wqs, FD, FD, FD, FD,
                g_part, (size_t)(8+z)*MNq, FD, mt*32, nt*128, z*2, z*2+2, As, Bs);
        } else {
            int uu = u - U_QP2;
            int z = uu % 14, nt = uu / 14;
            gemm_w<false,true,false>(g_avgp, BS, CATD, CATD, 4, (size_t)BS*CATD, 1.f/NB, nullptr, 1,
                Wvis, Wsem, FD, CATD, FD, SEM,
                g_part2, (size_t)z*SLABG, 1408, 0, nt*128, z*3, z*3+3, As, Bs);
        }
    }
    gsync(gen);

    // ===== S2: q reduce | gates reduce =====
    for (int u = blockIdx.x; u < S2U; u += NBLK) {
        if (u < U_QR) {
            size_t i4 = (size_t)u*256 + t;
            float4 v = make_float4(0,0,0,0);
#pragma unroll
            for (int z = 0; z < 13; z++) {
                float4 w = ((const float4*)g_part)[(size_t)z*(MNq/4) + i4];
                v.x+=w.x; v.y+=w.y; v.z+=w.z; v.w+=w.w;
            }
            ((float4*)g_q)[i4] = v;
        } else {
            size_t i = (size_t)(u - U_QR)*256 + t;
            if (i < (size_t)BS*CATD) {
                int m = (int)(i / CATD), n = (int)(i % CATD);
                float v = 0.f;
#pragma unroll
                for (int z = 0; z < 14; z++) v += g_part2[(size_t)z*SLABG + (size_t)m*1408 + n];
                if (n < FD) {
                    v += bvis[n];
                    g_gv[(size_t)m*FD + n] = 1.f + 1.f/(1.f + __expf(-v));
                } else {
                    v += bsem[n - FD];
                    g_gs[(size_t)m*SEM + (n - FD)] = 1.f + 1.f/(1.f + __expf(-v));
                }
            }
        }
    }
    gsync(gen);

    // ===== S3: qk (q @ [Wk;Wks]^T, B transposed) =====
    for (int u = blockIdx.x; u < 440; u += NBLK) {
        int z = u & 7, r = u >> 3;
        int nt = r % 11, mt = r / 11;
        gemm_w<true,false,false>(g_q, BTOT, FD, FD, 0, 0, 1.f, nullptr, 1,
            Wk, Wks, FD, CATD, FD, FD,
            g_part, (size_t)z*SLABK, 1408, mt*32, nt*128, z*4, z*4+4, As, Bs);
    }
    gsync(gen);

    // ===== S4: qk reduce * gates =====
    for (int u = blockIdx.x; u < 828; u += NBLK) {
        size_t i = (size_t)u*256 + t;
        if (i < (size_t)MNk) {
            int m = (int)(i / CATD), n = (int)(i % CATD);
            float v = 0.f;
#pragma unroll
            for (int z = 0; z < 8; z++) v += g_part[(size_t)z*SLABK + (size_t)m*1408 + n];
            int b = m / NWAY;
            if (n < FD) g_qkg [(size_t)m*FD  + n]      = v * g_gv[(size_t)b*FD  + n];
            else        g_qksg[(size_t)m*SEM + (n-FD)] = v * g_gs[(size_t)b*SEM + (n-FD)];
        }
    }
    gsync(gen);

    // ===== S5: scores =====
    for (int u = blockIdx.x; u < 512; u += NBLK) {
        int b = u / 16, ch = u % 16;
        int w = t >> 5, lane = t & 31;
        int nbase = ch*32 + w*4;
        float acc[4][5];
#pragma unroll
        for (int j = 0; j < 4; j++)
#pragma unroll
            for (int p = 0; p < 5; p++) acc[j][p] = 0.f;
        const float4* qkg4 = (const float4*)g_qkg  + (size_t)b*NWAY*(FD/4);
        const float4* qks4 = (const float4*)g_qksg + (size_t)b*NWAY*(SEM/4);
        const float4* bw4  = (const float4*)bw     + (size_t)b*NB*(FD/4);
        const float4* bs4  = (const float4*)bsm    + (size_t)b*NB*(SEM/4);
#pragma unroll
        for (int tt = 0; tt < 8; tt++) {
            int c = tt*32 + lane;
            float4 qv[5];
#pragma unroll
            for (int p = 0; p < 5; p++) qv[p] = qkg4[p*(FD/4) + c];
#pragma unroll
            for (int j = 0; j < 4; j++) {
                float4 x = bw4[(size_t)(nbase+j)*(FD/4) + c];
#pragma unroll
                for (int p = 0; p < 5; p++) acc[j][p] += d4(x, qv[p]);
            }
        }
#pragma unroll
        for (int tt = 0; tt < 3; tt++) {
            int c = tt*32 + lane;
            bool ok = c < (SEM/4);
            float4 qv[5];
#pragma unroll
            for (int p = 0; p < 5; p++)
                qv[p] = ok ? qks4[p*(SEM/4) + c] : make_float4(0,0,0,0);
#pragma unroll
            for (int j = 0; j < 4; j++) {
                float4 x = ok ? bs4[(size_t)(nbase+j)*(SEM/4) + c] : make_float4(0,0,0,0);
#pragma unroll
                for (int p = 0; p < 5; p++) acc[j][p] += d4(x, qv[p]);
            }
        }
#pragma unroll
        for (int off = 16; off; off >>= 1)
#pragma unroll
            for (int j = 0; j < 4; j++)
#pragma unroll
                for (int p = 0; p < 5; p++)
                    acc[j][p] += __shfl_xor_sync(0xffffffffu, acc[j][p], off);
#pragma unroll
        for (int j = 0; j < 4; j++)
            if (lane == j) {
                int n = nbase + j;
#pragma unroll
                for (int p = 0; p < 5; p++)
                    g_scr[(size_t)(b*NWAY+p)*NB + n] = acc[j][p] * (1.f/32.f);
            }
    }
    gsync(gen);

    // ===== S6: softmax over 512 =====
    for (int u = blockIdx.x; u < BTOT; u += NBLK) {
        float v0 = g_scr[(size_t)u*NB + t], v1 = g_scr[(size_t)u*NB + 256 + t];
        sm[t] = fmaxf(v0, v1); __syncthreads();
        for (int s = 128; s; s >>= 1) { if (t < s) sm[t] = fmaxf(sm[t], sm[t+s]); __syncthreads(); }
        float mx = sm[0]; __syncthreads();
        float e0 = __expf(v0 - mx), e1 = __expf(v1 - mx);
        sm[t] = e0 + e1; __syncthreads();
        for (int s = 128; s; s >>= 1) { if (t < s) sm[t] += sm[t+s]; __syncthreads(); }
        float inv = 1.f / sm[0]; __syncthreads();
        g_scr[(size_t)u*NB + t] = e0*inv;
        g_scr[(size_t)u*NB + 256 + t] = e1*inv;
    }
    gsync(gen);

    // ===== S7: nway-averaged attention @ bw  (mixavg partials, [32,1024]) =====
    for (int u = blockIdx.x; u < 128; u += NBLK) {
        int b = u >> 2, chunk = u & 3;
        if (t < 128) {
            float s = 0.f;
#pragma unroll
            for (int p = 0; p < NWAY; p++)
                s += g_scr[(size_t)(b*NWAY+p)*NB + chunk*128 + t];
            sm[t] = s * (1.f/NWAY);
        }
        __syncthreads();
        float4 acc = make_float4(0,0,0,0);
        const float4* p = (const float4*)bw + ((size_t)b*NB + chunk*128)*(FD/4) + t;
#pragma unroll 8
        for (int n = 0; n < 128; n++) {
            float4 x = p[(size_t)n*(FD/4)];
            float a = sm[n];
            acc.x = fmaf(x.x, a, acc.x); acc.y = fmaf(x.y, a, acc.y);
            acc.z = fmaf(x.z, a, acc.z); acc.w = fmaf(x.w, a, acc.w);
        }
        ((float4*)g_mixp)[(size_t)chunk*(SLABF/4) + (size_t)b*(FD/4) + t] = acc;
        __syncthreads();
    }
    gsync(gen);

    // ===== S8: fakev = (mixavg * gv) @ Wv  (M=32) =====
    for (int u = blockIdx.x; u < 32; u += NBLK) {
        int z = u & 3, nt = u >> 2;
        gemm_w<false,true,true>(g_mixp, BS, FD, FD, 4, (size_t)SLABF, 1.f, g_gv, 1,
            Wv, Wv, FD, FD, FD, FD,
            g_part, (size_t)z*SLABF, FD, 0, nt*128, z*8, z*8+8, As, Bs);
    }
    gsync(gen);

    // ===== S9: fakefc = reduce(fakev) @ Wfc =====
    for (int u = blockIdx.x; u < 32; u += NBLK) {
        int z = u & 3, nt = u >> 2;
        gemm_w<false,true,false>(g_part, BS, FD, FD, 4, (size_t)SLABF, 1.f, nullptr, 1,
            Wfc, Wfc, FD, FD, FD, FD,
            g_part, (size_t)(4+z)*SLABF, FD, 0, nt*128, z*8, z*8+8, As, Bs);
    }
    gsync(gen);

    // ===== S10: fake + norms + logits =====
    for (int u = blockIdx.x; u < BS*10; u += NBLK) {
        int b = u / 10, qc = u % 10;
        {
            const float4* sc4 = (const float4*)sc + (size_t)b*NWAY*(FD/4);
            float4 f = make_float4(0,0,0,0);
            float sq[6];
#pragma unroll
            for (int c = 0; c < NWAY; c++) {
                float4 o = sc4[c*(FD/4) + t];
                sq[c] = d4(o, o);
                f.x+=o.x; f.y+=o.y; f.z+=o.z; f.w+=o.w;
            }
            f.x*=0.2f; f.y*=0.2f; f.z*=0.2f; f.w*=0.2f;
#pragma unroll
            for (int z = 4; z < 8; z++) {
                float4 w = ((const float4*)g_part)[(size_t)z*(SLABF/4) + (size_t)b*(FD/4) + t];
                f.x+=w.x; f.y+=w.y; f.z+=w.z; f.w+=w.w;
            }
            ((float4*)sm)[t] = f;
            sq[5] = d4(f, f);
#pragma unroll
            for (int off = 16; off; off >>= 1)
#pragma unroll
                for (int r = 0; r < 6; r++)
                    sq[r] += __shfl_xor_sync(0xffffffffu, sq[r], off);
            int lane = t & 31, w = t >> 5;
            if (lane == 0)
#pragma unroll
                for (int r = 0; r < 6; r++) sm[1024 + w*6 + r] = sq[r];
            __syncthreads();
            if (t < 6) {
                float s = 0.f;
                for (int w2 = 0; w2 < 8; w2++) s += sm[1024 + w2*6 + t];
                sm[1072 + t] = 1.f / sqrtf(s);
            }
            __syncthreads();
        }
        {
            int w = t >> 5, lane = t & 31;
            int iq = qc*8 + w;
            if (iq < NQ) {
                const float4* q4  = (const float4*)qf + ((size_t)b*NQ + iq)*(FD/4);
                const float4* sc4 = (const float4*)sc + (size_t)b*NWAY*(FD/4);
                const float4* f4  = (const float4*)sm;
                float qq = 0.f, d[6] = {0,0,0,0,0,0};
                for (int i = lane; i < FD/4; i += 32) {
                    float4 x = q4[i];
                    qq += d4(x, x);
#pragma unroll
                    for (int r = 0; r < NWAY; r++) d[r] += d4(x, sc4[r*(FD/4) + i]);
                    d[5] += d4(x, f4[i]);
                }
#pragma unroll
                for (int off = 16; off; off >>= 1) {
                    qq += __shfl_xor_sync(0xffffffffu, qq, off);
#pragma unroll
                    for (int r = 0; r < 6; r++) d[r] += __shfl_xor_sync(0xffffffffu, d[r], off);
                }
                if (lane == 0) {
                    float s = temp[0] / sqrtf(qq);
                    float* o = outL + ((size_t)b*NQ + iq)*6;
#pragma unroll
                    for (int r = 0; r < 6; r++) o[r] = d[r] * s * sm[1072 + r];
                }
            }
        }
        __syncthreads();
    }
}

// ---------------- host ----------------
extern "C" void kernel_launch(void* const* d_in, const int* in_sizes, int n_in,
                              void* d_out, int out_size)
{
    const float* sc   = (const float*)d_in[0];
    const float* bw   = (const float*)d_in[1];
    const float* ss   = (const float*)d_in[2];
    const float* bsm  = (const float*)d_in[3];
    const float* qf   = (const float*)d_in[4];
    const float* Wm1  = (const float*)d_in[5];
    const float* bm1  = (const float*)d_in[6];
    const float* Wm2  = (const float*)d_in[7];
    const float* bm2  = (const float*)d_in[8];
    const float* Wvis = (const float*)d_in[9];
    const float* bvis = (const float*)d_in[10];
    const float* Wsem = (const float*)d_in[11];
    const float* bsem = (const float*)d_in[12];
    const float* Wq   = (const float*)d_in[13];
    const float* Wk   = (const float*)d_in[14];
    const float* Wv   = (const float*)d_in[15];
    const float* Wqs  = (const float*)d_in[16];
    const float* Wks  = (const float*)d_in[17];
    const float* Wfc  = (const float*)d_in[18];
    const float* temp = (const float*)d_in[19];
    float* out = (float*)d_out;

    int dev = 0;
    cudaGetDevice(&dev);
    int nsm = 148;
    cudaDeviceGetAttribute(&nsm, cudaDevAttrMultiProcessorCount, dev);
    int bpm = 1;
    cudaOccupancyMaxActiveBlocksPerMultiprocessor(&bpm, fused_k, 256, 0);
    if (bpm < 1) bpm = 1;
    int nblk = nsm * bpm;

    void* barp = nullptr;
    cudaGetSymbolAddress(&barp, g_barrier);
    cudaMemsetAsync(barp, 0, sizeof(unsigned int), 0);

    fused_k<<<nblk, 256>>>(sc, bw, ss, bsm, qf, Wm1, bm1, Wm2, bm2,
                           Wvis, bvis, Wsem, bsem, Wq, Wk, Wv, Wqs, Wks, Wfc,
                           temp, out);
}

// round 8
// speedup vs baseline: 2.0447x; 1.1578x over previous
#include <cuda_runtime.h>
#include <mma.h>
#include <math.h>
#include <cstdint>

using namespace nvcuda;

#define FD    1024
#define SEM   300
#define NWAY  5
#define BS    32
#define NB    512
#define NQ    75
#define BTOT  (BS*NWAY)     // 160
#define CATD  (FD+SEM)      // 1324

#define MNq   (BTOT*FD)     // 163840
#define MNk   (BTOT*CATD)   // 211840
#define SLABK (BTOT*1408)   // padded qk partial slab
#define SLABG (BS*1408)
#define SLABF (BS*FD)       // 32768

#define SMEMF 12800         // dynamic smem floats (2 x 6400 gemm buffers)
#define BUFF  6400

// ---------------- scratch ----------------
__device__ __align__(32) float g_scal[BTOT*SEM];
__device__ __align__(32) float g_gv  [BS*FD];
__device__ __align__(32) float g_gs  [BS*SEM];
__device__ __align__(32) float g_q   [BTOT*FD];
__device__ __align__(32) float g_qkg [BTOT*FD];
__device__ __align__(32) float g_qksg[BTOT*SEM];
__device__ __align__(32) float g_scr [BTOT*NB];
__device__ __align__(32) float g_avgp[4*BS*CATD];
__device__ __align__(32) float g_mixp[8*SLABF];
__device__ __align__(32) float g_part [16*MNq];
__device__ __align__(32) float g_part2[14*SLABG];
__device__ unsigned int g_barrier;

// ---------------- software grid barrier ----------------
__device__ __forceinline__ void gsync(int &gen)
{
    __syncthreads();
    if (threadIdx.x == 0) {
        __threadfence();
        atomicAdd(&g_barrier, 1u);
        unsigned target = (unsigned)gridDim.x * (unsigned)gen;
        unsigned v;
        do {
            asm volatile("ld.acquire.gpu.u32 %0, [%1];" : "=r"(v) : "l"(&g_barrier) : "memory");
            if (v >= target) break;
            __nanosleep(32);
        } while (true);
    }
    __syncthreads();
    gen++;
}

__device__ __forceinline__ float d4(float4 a, float4 b)
{ return a.x*b.x + a.y*b.y + a.z*b.z + a.w*b.w; }

// L2 evict_last access policy (created once per thread)
__device__ __forceinline__ uint64_t mkpolicy()
{
    uint64_t p;
    asm volatile("createpolicy.fractional.L2::evict_last.b64 %0, 1.0;" : "=l"(p));
    return p;
}

// evict-last vector load via cache_hint (keeps base bank L2-resident)
__device__ __forceinline__ float4 ldg_el(const float4* p, uint64_t pol)
{
    float4 v;
    asm volatile("ld.global.L2::cache_hint.v4.f32 {%0,%1,%2,%3}, [%4], %5;"
        : "=f"(v.x), "=f"(v.y), "=f"(v.z), "=f"(v.w) : "l"(p), "l"(pol));
    return v;
}

// cp.async 16B with zero-fill predicate
__device__ __forceinline__ void cp16(uint32_t saddr, const void* g, bool pred)
{
    asm volatile("cp.async.ca.shared.global [%0], [%1], 16, %2;"
        :: "r"(saddr), "l"(g), "r"(pred ? 16 : 0));
}

typedef wmma::fragment<wmma::matrix_a, 16,16,8, wmma::precision::tf32, wmma::row_major> FragA;
typedef wmma::fragment<wmma::matrix_b, 16,16,8, wmma::precision::tf32, wmma::row_major> FragBR;
typedef wmma::fragment<wmma::matrix_b, 16,16,8, wmma::precision::tf32, wmma::col_major> FragBC;
typedef wmma::fragment<wmma::accumulator, 16,16,8, float> FragC;

template<class F>
__device__ __forceinline__ void split_frag(F& hi, F& lo)
{
#pragma unroll
    for (int i = 0; i < hi.num_elements; i++) {
        float r = hi.x[i];
        float h = wmma::__float_to_tf32(r);
        hi.x[i] = h;
        lo.x[i] = wmma::__float_to_tf32(r - h);
    }
}

// ---------------- mma on one staged buffer ----------------
template<bool BTR>
__device__ __forceinline__ void mma_tile(float* As, float* Bs, int mrow, int nq,
                                         FragC& c0, FragC& c1)
{
#pragma unroll
    for (int kk = 0; kk < 32; kk += 8) {
        FragA ah, al;
        wmma::load_matrix_sync(ah, As + mrow*16*40 + kk, 40);
        split_frag(ah, al);
        if (!BTR) {
            FragBR b0h,b0l,b1h,b1l;
            wmma::load_matrix_sync(b0h, Bs + kk*136 + nq*32, 136);
            wmma::load_matrix_sync(b1h, Bs + kk*136 + nq*32 + 16, 136);
            split_frag(b0h, b0l); split_frag(b1h, b1l);
            wmma::mma_sync(c0, ah, b0h, c0);
            wmma::mma_sync(c0, ah, b0l, c0);
            wmma::mma_sync(c0, al, b0h, c0);
            wmma::mma_sync(c1, ah, b1h, c1);
            wmma::mma_sync(c1, ah, b1l, c1);
            wmma::mma_sync(c1, al, b1h, c1);
        } else {
            FragBC b0h,b0l,b1h,b1l;
            wmma::load_matrix_sync(b0h, Bs + (nq*32)*40 + kk, 40);
            wmma::load_matrix_sync(b1h, Bs + (nq*32+16)*40 + kk, 40);
            split_frag(b0h, b0l); split_frag(b1h, b1l);
            wmma::mma_sync(c0, ah, b0h, c0);
            wmma::mma_sync(c0, ah, b0l, c0);
            wmma::mma_sync(c0, al, b0h, c0);
            wmma::mma_sync(c1, ah, b1h, c1);
            wmma::mma_sync(c1, ah, b1l, c1);
            wmma::mma_sync(c1, al, b1h, c1);
        }
    }
}

// ---------------- cp.async double-buffered plain GEMM (A plain row-major) ----------------
template<bool BTR>
__device__ __forceinline__ void gemm_pipe(
    const float* __restrict__ A, int M, int K, int lda,
    const float* __restrict__ B1, const float* __restrict__ B2,
    int N1, int N, int ldb1, int ldb2,
    float* __restrict__ part, size_t slab, int ldp,
    int m0, int n0, int kt0, int kt1, float* __restrict__ smbase)
{
    const int t = threadIdx.x;
    const int warp = t >> 5, mrow = warp >> 2, nq = warp & 3;
    FragC c0, c1;
    wmma::fill_fragment(c0, 0.f);
    wmma::fill_fragment(c1, 0.f);

    auto issue = [&](int kt, int bufi) {
        float* As = smbase + bufi*BUFF;
        float* Bs = As + 1280;
        int k0 = kt*32;
        {
            int mm = t >> 3, kq = t & 7;
            int mg = m0 + mm, kg = k0 + kq*4;
            bool ok = (mg < M) && (kg < K);
            uint32_t sa = (uint32_t)__cvta_generic_to_shared(&As[mm*40 + kq*4]);
            cp16(sa, &A[(size_t)mg*lda + kg], ok);
        }
        if (!BTR) {
            int kk = t >> 3, cc = t & 7;
            int kg = k0 + kk;
#pragma unroll
            for (int j = 0; j < 4; j++) {
                int nn = (cc + 8*j)*4;
                int ng = n0 + nn;
                bool ok = (kg < K) && (ng < N);
                const float* g = (ng < N1) ? &B1[(size_t)kg*ldb1 + ng]
                                           : &B2[(size_t)kg*ldb2 + (ng - N1)];
                uint32_t sa = (uint32_t)__cvta_generic_to_shared(&Bs[kk*136 + nn]);
                cp16(sa, g, ok);
            }
        } else {
            int n = t >> 1, half = t & 1;
            int ng = n0 + n;
            bool okrow = ng < N;
            const float* brow = okrow ? ((ng < N1) ? &B1[(size_t)ng*ldb1]
                                                   : &B2[(size_t)(ng-N1)*ldb2]) : B1;
#pragma unroll
            for (int j = 0; j < 4; j++) {
                int kg = k0 + half*16 + j*4;
                bool ok = okrow && (kg < K);
                uint32_t sa = (uint32_t)__cvta_generic_to_shared(&Bs[n*40 + half*16 + j*4]);
                cp16(sa, &brow[kg], ok);
            }
        }
        asm volatile("cp.async.commit_group;");
    };

    issue(kt0, 0);
    for (int kt = kt0; kt < kt1; kt++) {
        int bufi = (kt - kt0) & 1;
        bool more = (kt + 1 < kt1);
        if (more) issue(kt + 1, bufi ^ 1);
        if (more) asm volatile("cp.async.wait_group 1;");
        else      asm volatile("cp.async.wait_group 0;");
        __syncthreads();
        float* As = smbase + bufi*BUFF;
        mma_tile<BTR>(As, As + 1280, mrow, nq, c0, c1);
        __syncthreads();
    }
    float* cb = part + slab + (size_t)(m0 + mrow*16)*ldp + n0 + nq*32;
    wmma::store_matrix_sync(cb,      c0, ldp, wmma::mem_row_major);
    wmma::store_matrix_sync(cb + 16, c1, ldp, wmma::mem_row_major);
}

// ---------------- generic GEMM with A-side reduce/gate (small stages) ----------------
template<bool REDA, bool GATEA>
__device__ __forceinline__ void gemm_w(
    const float* __restrict__ A, int M, int K, int lda,
    int Zred, size_t slabA, float ascale, const float* __restrict__ gateA,
    const float* __restrict__ B1, const float* __restrict__ B2,
    int N1, int N, int ldb1, int ldb2,
    float* __restrict__ part, size_t slab, int ldp,
    int m0, int n0, int kt0, int kt1, float* __restrict__ smbase)
{
    const int t = threadIdx.x;
    const int warp = t >> 5, mrow = warp >> 2, nq = warp & 3;
    float* As = smbase;
    float* Bs = smbase + 1280;
    FragC c0, c1;
    wmma::fill_fragment(c0, 0.f);
    wmma::fill_fragment(c1, 0.f);

    for (int kt = kt0; kt < kt1; kt++) {
        int k0 = kt*32;
        {
            int mm = t >> 3, kq = (t & 7)*4;
            int mg = m0 + mm, kg = k0 + kq;
            float4 v = make_float4(0,0,0,0);
            if (mg < M && kg + 3 < K) {
                if (REDA) {
                    for (int z = 0; z < Zred; z++) {
                        float4 w = *(const float4*)&A[(size_t)z*slabA + (size_t)mg*lda + kg];
                        v.x+=w.x; v.y+=w.y; v.z+=w.z; v.w+=w.w;
                    }
                } else v = *(const float4*)&A[(size_t)mg*lda + kg];
                v.x*=ascale; v.y*=ascale; v.z*=ascale; v.w*=ascale;
                if (GATEA) {
                    float4 g = *(const float4*)&gateA[(size_t)mg*lda + kg];
                    v.x*=g.x; v.y*=g.y; v.z*=g.z; v.w*=g.w;
                }
            } else if (mg < M) {
                float tmp[4] = {0,0,0,0};
                for (int j = 0; j < 4; j++) {
                    int k2 = kg + j;
                    if (k2 < K) {
                        float s = 0.f;
                        if (REDA) { for (int z=0; z<Zred; z++) s += A[(size_t)z*slabA + (size_t)mg*lda + k2]; }
                        else s = A[(size_t)mg*lda + k2];
                        s *= ascale;
                        if (GATEA) s *= gateA[(size_t)mg*lda + k2];
                        tmp[j] = s;
                    }
                }
                v = make_float4(tmp[0],tmp[1],tmp[2],tmp[3]);
            }
            *(float4*)&As[ (t>>3)*40 + (t&7)*4 ] = v;
        }
        {
            int kk = t >> 3, cc = t & 7;
            int kg = k0 + kk;
#pragma unroll
            for (int j = 0; j < 4; j++) {
                int nn = (cc + 8*j)*4;
                int ng = n0 + nn;
                float4 v = make_float4(0,0,0,0);
                if (kg < K && ng < N) {
                    if (ng < N1) v = *(const float4*)&B1[(size_t)kg*ldb1 + ng];
                    else         v = *(const float4*)&B2[(size_t)kg*ldb2 + (ng-N1)];
                }
                *(float4*)&Bs[kk*136 + nn] = v;
            }
        }
        __syncthreads();
        mma_tile<false>(As, Bs, mrow, nq, c0, c1);
        __syncthreads();
    }
    float* cb = part + slab + (size_t)(m0 + mrow*16)*ldp + n0 + nq*32;
    wmma::store_matrix_sync(cb,      c0, ldp, wmma::mem_row_major);
    wmma::store_matrix_sync(cb + 16, c1, ldp, wmma::mem_row_major);
}

// stage unit counts
#define U_MLP   40
#define U_QP1   320
#define U_AVG   256
#define S0U     (U_MLP+U_QP1+U_AVG)
#define U_QP2   200
#define U_GAT   154
#define S1U     (U_QP2+U_GAT)
#define U_QR    160
#define U_GR    166
#define S2U     (U_QR+U_GR)

__global__ void __launch_bounds__(256, 2) fused_k(
    const float* __restrict__ sc,  const float* __restrict__ bw,
    const float* __restrict__ ss,  const float* __restrict__ bsm,
    const float* __restrict__ qf,
    const float* __restrict__ Wm1, const float* __restrict__ bm1,
    const float* __restrict__ Wm2, const float* __restrict__ bm2,
    const float* __restrict__ Wvis,const float* __restrict__ bvis,
    const float* __restrict__ Wsem,const float* __restrict__ bsem,
    const float* __restrict__ Wq,  const float* __restrict__ Wk,
    const float* __restrict__ Wv,  const float* __restrict__ Wqs,
    const float* __restrict__ Wks, const float* __restrict__ Wfc,
    const float* __restrict__ temp, float* __restrict__ outL)
{
    extern __shared__ __align__(32) float sm[];
    const int NBLK = gridDim.x;
    const int t = threadIdx.x;
    const uint64_t pol = mkpolicy();
    int gen = 1;

    // ===== S0: MLP | qp1 (sc@Wq, pipelined) | avg partials (evict_last) =====
    for (int u = blockIdx.x; u < S0U; u += NBLK) {
        if (u < U_MLP) {
            int m0u = u * 4;
            for (int i = t; i < 4*SEM; i += 256)
                sm[i] = ss[(size_t)(m0u + i/SEM)*SEM + (i % SEM)];
            __syncthreads();
            for (int n = t; n < SEM; n += 256) {
                float a0 = bm1[n], a1 = a0, a2 = a0, a3 = a0;
                for (int k = 0; k < SEM; k++) {
                    float w = Wm1[(size_t)k*SEM + n];
                    a0 = fmaf(sm[0*SEM+k], w, a0); a1 = fmaf(sm[1*SEM+k], w, a1);
                    a2 = fmaf(sm[2*SEM+k], w, a2); a3 = fmaf(sm[3*SEM+k], w, a3);
                }
                sm[1280 + 0*SEM + n] = (a0 >= 0.f) ? a0 : 0.1f*a0;
                sm[1280 + 1*SEM + n] = (a1 >= 0.f) ? a1 : 0.1f*a1;
                sm[1280 + 2*SEM + n] = (a2 >= 0.f) ? a2 : 0.1f*a2;
                sm[1280 + 3*SEM + n] = (a3 >= 0.f) ? a3 : 0.1f*a3;
            }
            __syncthreads();
            for (int n = t; n < SEM; n += 256) {
                float a0 = bm2[n], a1 = a0, a2 = a0, a3 = a0;
                for (int k = 0; k < SEM; k++) {
                    float w = Wm2[(size_t)k*SEM + n];
                    a0 = fmaf(sm[1280+0*SEM+k], w, a0); a1 = fmaf(sm[1280+1*SEM+k], w, a1);
                    a2 = fmaf(sm[1280+2*SEM+k], w, a2); a3 = fmaf(sm[1280+3*SEM+k], w, a3);
                }
                g_scal[(size_t)(m0u+0)*SEM + n] = a0;
                g_scal[(size_t)(m0u+1)*SEM + n] = a1;
                g_scal[(size_t)(m0u+2)*SEM + n] = a2;
                g_scal[(size_t)(m0u+3)*SEM + n] = a3;
            }
            __syncthreads();
        } else if (u < U_MLP + U_QP1) {
            int uu = u - U_MLP;
            int z = uu & 7, r = uu >> 3;
            int nt = r & 7, mt = r >> 3;
            gemm_pipe<false>(sc, BTOT, FD, FD, Wq, Wq, FD, FD, FD, FD,
                g_part, (size_t)z*MNq, FD, mt*32, nt*128, z*4, z*4+4, sm);
        } else {
            int uu = u - (U_MLP+U_QP1);
            int chunk = uu >> 6, r = uu & 63;
            int b = r >> 1, cpart = r & 1;
            int c4 = cpart*256 + t;
            if (c4 < CATD/4) {
                int c = c4*4;
                int n0 = chunk*128;
                float4 v = make_float4(0,0,0,0);
                if (c < FD) {
                    const float4* p = (const float4*)bw + ((size_t)b*NB + n0)*(FD/4) + c4;
#pragma unroll 8
                    for (int n = 0; n < 128; n++) {
                        float4 x = ldg_el(&p[(size_t)n*(FD/4)], pol);
                        v.x+=x.x; v.y+=x.y; v.z+=x.z; v.w+=x.w;
                    }
                } else {
                    const float4* p = (const float4*)(bsm + ((size_t)b*NB + n0)*SEM + (c-FD));
#pragma unroll 8
                    for (int n = 0; n < 128; n++) {
                        float4 x = ldg_el(&p[(size_t)n*(SEM/4)], pol);
                        v.x+=x.x; v.y+=x.y; v.z+=x.z; v.w+=x.w;
                    }
                }
                *(float4*)&g_avgp[(size_t)chunk*BS*CATD + (size_t)b*CATD + c] = v;
            }
        }
    }
    gsync(gen);

    // ===== S1: qp2 (s@Wqs, pipelined) | gates (REDA avg) =====
    for (int u = blockIdx.x; u < S1U; u += NBLK) {
        if (u < U_QP2) {
            int z = u % 5, r = u / 5;
            int nt = r & 7, mt = r >> 3;
            gemm_pipe<false>(g_scal, BTOT, SEM, SEM, Wqs, Wqs, FD, FD, FD, FD,
                g_part, (size_t)(8+z)*MNq, FD, mt*32, nt*128, z*2, z*2+2, sm);
        } else {
            int uu = u - U_QP2;
            int z = uu % 14, nt = uu / 14;
            gemm_w<true,false>(g_avgp, BS, CATD, CATD, 4, (size_t)BS*CATD, 1.f/NB, nullptr,
                Wvis, Wsem, FD, CATD, FD, SEM,
                g_part2, (size_t)z*SLABG, 1408, 0, nt*128, z*3, z*3+3, sm);
        }
    }
    gsync(gen);

    // ===== S2: q reduce | gates reduce =====
    for (int u = blockIdx.x; u < S2U; u += NBLK) {
        if (u < U_QR) {
            size_t i4 = (size_t)u*256 + t;
            float4 v = make_float4(0,0,0,0);
#pragma unroll
            for (int z = 0; z < 13; z++) {
                float4 w = ((const float4*)g_part)[(size_t)z*(MNq/4) + i4];
                v.x+=w.x; v.y+=w.y; v.z+=w.z; v.w+=w.w;
            }
            ((float4*)g_q)[i4] = v;
        } else {
            size_t i = (size_t)(u - U_QR)*256 + t;
            if (i < (size_t)BS*CATD) {
                int m = (int)(i / CATD), n = (int)(i % CATD);
                float v = 0.f;
#pragma unroll
                for (int z = 0; z < 14; z++) v += g_part2[(size_t)z*SLABG + (size_t)m*1408 + n];
                if (n < FD) {
                    v += bvis[n];
                    g_gv[(size_t)m*FD + n] = 1.f + 1.f/(1.f + __expf(-v));
                } else {
                    v += bsem[n - FD];
                    g_gs[(size_t)m*SEM + (n - FD)] = 1.f + 1.f/(1.f + __expf(-v));
                }
            }
        }
    }
    gsync(gen);

    // ===== S3: qk (q @ [Wk;Wks]^T, pipelined BTR) =====
    for (int u = blockIdx.x; u < 440; u += NBLK) {
        int z = u & 7, r = u >> 3;
        int nt = r % 11, mt = r / 11;
        gemm_pipe<true>(g_q, BTOT, FD, FD, Wk, Wks, FD, CATD, FD, FD,
            g_part, (size_t)z*SLABK, 1408, mt*32, nt*128, z*4, z*4+4, sm);
    }
    gsync(gen);

    // ===== S4: qk reduce * gates =====
    for (int u = blockIdx.x; u < 828; u += NBLK) {
        size_t i = (size_t)u*256 + t;
        if (i < (size_t)MNk) {
            int m = (int)(i / CATD), n = (int)(i % CATD);
            float v = 0.f;
#pragma unroll
            for (int z = 0; z < 8; z++) v += g_part[(size_t)z*SLABK + (size_t)m*1408 + n];
            int b = m / NWAY;
            if (n < FD) g_qkg [(size_t)m*FD  + n]      = v * g_gv[(size_t)b*FD  + n];
            else        g_qksg[(size_t)m*SEM + (n-FD)] = v * g_gs[(size_t)b*SEM + (n-FD)];
        }
    }
    gsync(gen);

    // ===== S5: scores (bank loaded evict_last) =====
    for (int u = blockIdx.x; u < 512; u += NBLK) {
        int b = u / 16, ch = u % 16;
        int w = t >> 5, lane = t & 31;
        int nbase = ch*32 + w*4;
        float acc[4][5];
#pragma unroll
        for (int j = 0; j < 4; j++)
#pragma unroll
            for (int p = 0; p < 5; p++) acc[j][p] = 0.f;
        const float4* qkg4 = (const float4*)g_qkg  + (size_t)b*NWAY*(FD/4);
        const float4* qks4 = (const float4*)g_qksg + (size_t)b*NWAY*(SEM/4);
        const float4* bw4  = (const float4*)bw     + (size_t)b*NB*(FD/4);
        const float4* bs4  = (const float4*)bsm    + (size_t)b*NB*(SEM/4);
#pragma unroll
        for (int tt = 0; tt < 8; tt++) {
            int c = tt*32 + lane;
            float4 qv[5];
#pragma unroll
            for (int p = 0; p < 5; p++) qv[p] = qkg4[p*(FD/4) + c];
#pragma unroll
            for (int j = 0; j < 4; j++) {
                float4 x = ldg_el(&bw4[(size_t)(nbase+j)*(FD/4) + c], pol);
#pragma unroll
                for (int p = 0; p < 5; p++) acc[j][p] += d4(x, qv[p]);
            }
        }
#pragma unroll
        for (int tt = 0; tt < 3; tt++) {
            int c = tt*32 + lane;
            bool ok = c < (SEM/4);
            float4 qv[5];
#pragma unroll
            for (int p = 0; p < 5; p++)
                qv[p] = ok ? qks4[p*(SEM/4) + c] : make_float4(0,0,0,0);
#pragma unroll
            for (int j = 0; j < 4; j++) {
                float4 x = ok ? ldg_el(&bs4[(size_t)(nbase+j)*(SEM/4) + c], pol) : make_float4(0,0,0,0);
#pragma unroll
                for (int p = 0; p < 5; p++) acc[j][p] += d4(x, qv[p]);
            }
        }
#pragma unroll
        for (int off = 16; off; off >>= 1)
#pragma unroll
            for (int j = 0; j < 4; j++)
#pragma unroll
                for (int p = 0; p < 5; p++)
                    acc[j][p] += __shfl_xor_sync(0xffffffffu, acc[j][p], off);
#pragma unroll
        for (int j = 0; j < 4; j++)
            if (lane == j) {
                int n = nbase + j;
#pragma unroll
                for (int p = 0; p < 5; p++)
                    g_scr[(size_t)(b*NWAY+p)*NB + n] = acc[j][p] * (1.f/32.f);
            }
    }
    gsync(gen);

    // ===== S6: fused softmax + nway-avg attention + mix partials (256 units) =====
    for (int u = blockIdx.x; u < 256; u += NBLK) {
        int b = u >> 3, chunk = u & 7;
        int n0 = chunk*64;
        int w = t >> 5, lane = t & 31;
        for (int i = t; i < NWAY*NB; i += 256)
            sm[i] = g_scr[(size_t)b*NWAY*NB + i];
        __syncthreads();
        float mx[5];
#pragma unroll
        for (int p = 0; p < 5; p++)
            mx[p] = fmaxf(sm[p*NB + t], sm[p*NB + 256 + t]);
#pragma unroll
        for (int off = 16; off; off >>= 1)
#pragma unroll
            for (int p = 0; p < 5; p++)
                mx[p] = fmaxf(mx[p], __shfl_xor_sync(0xffffffffu, mx[p], off));
        if (lane == 0)
#pragma unroll
            for (int p = 0; p < 5; p++) sm[2624 + w*5 + p] = mx[p];
        __syncthreads();
        if (t < 5) {
            float m = sm[2624 + t];
            for (int w2 = 1; w2 < 8; w2++) m = fmaxf(m, sm[2624 + w2*5 + t]);
            sm[2680 + t] = m;
        }
        __syncthreads();
        float sme[5];
#pragma unroll
        for (int p = 0; p < 5; p++) {
            float m = sm[2680 + p];
            sme[p] = __expf(sm[p*NB + t] - m) + __expf(sm[p*NB + 256 + t] - m);
        }
#pragma unroll
        for (int off = 16; off; off >>= 1)
#pragma unroll
            for (int p = 0; p < 5; p++)
                sme[p] += __shfl_xor_sync(0xffffffffu, sme[p], off);
        if (lane == 0)
#pragma unroll
            for (int p = 0; p < 5; p++) sm[2624 + w*5 + p] = sme[p];
        __syncthreads();
        if (t < 5) {
            float s = 0.f;
            for (int w2 = 0; w2 < 8; w2++) s += sm[2624 + w2*5 + t];
            sm[2688 + t] = 1.f / s;
        }
        __syncthreads();
        if (t < 64) {
            int n = n0 + t;
            float a = 0.f;
#pragma unroll
            for (int p = 0; p < 5; p++)
                a += __expf(sm[p*NB + n] - sm[2680 + p]) * sm[2688 + p];
            sm[2696 + t] = a * (1.f/NWAY);
        }
        __syncthreads();
        float4 acc = make_float4(0,0,0,0);
        const float4* p4 = (const float4*)bw + ((size_t)b*NB + n0)*(FD/4) + t;
#pragma unroll 8
        for (int r = 0; r < 64; r++) {
            float4 x = p4[(size_t)r*(FD/4)];
            float a = sm[2696 + r];
            acc.x = fmaf(x.x, a, acc.x); acc.y = fmaf(x.y, a, acc.y);
            acc.z = fmaf(x.z, a, acc.z); acc.w = fmaf(x.w, a, acc.w);
        }
        ((float4*)g_mixp)[(size_t)chunk*(SLABF/4) + (size_t)b*(FD/4) + t] = acc;
        __syncthreads();
    }
    gsync(gen);

    // ===== S7: fakev = (mixavg * gv) @ Wv, split-K 16 =====
    for (int u = blockIdx.x; u < 128; u += NBLK) {
        int z = u & 15, nt = u >> 4;
        gemm_w<true,true>(g_mixp, BS, FD, FD, 8, (size_t)SLABF, 1.f, g_gv,
            Wv, Wv, FD, FD, FD, FD,
            g_part, (size_t)z*SLABF, FD, 0, nt*128, z*2, z*2+2, sm);
    }
    gsync(gen);

    // ===== S8: fakefc = reduce(fakev) @ Wfc, split-K 16 =====
    for (int u = blockIdx.x; u < 128; u += NBLK) {
        int z = u & 15, nt = u >> 4;
        gemm_w<true,false>(g_part, BS, FD, FD, 16, (size_t)SLABF, 1.f, nullptr,
            Wfc, Wfc, FD, FD, FD, FD,
            g_part, (size_t)(16+z)*SLABF, FD, 0, nt*128, z*2, z*2+2, sm);
    }
    gsync(gen);

    // ===== S9: fake + norms + logits =====
    for (int u = blockIdx.x; u < BS*10; u += NBLK) {
        int b = u / 10, qc = u % 10;
        {
            const float4* sc4 = (const float4*)sc + (size_t)b*NWAY*(FD/4);
            float4 f = make_float4(0,0,0,0);
            float sq[6];
#pragma unroll
            for (int c = 0; c < NWAY; c++) {
                float4 o = sc4[c*(FD/4) + t];
                sq[c] = d4(o, o);
                f.x+=o.x; f.y+=o.y; f.z+=o.z; f.w+=o.w;
            }
            f.x*=0.2f; f.y*=0.2f; f.z*=0.2f; f.w*=0.2f;
#pragma unroll
            for (int z = 16; z < 32; z++) {
                float4 w2 = ((const float4*)g_part)[(size_t)z*(SLABF/4) + (size_t)b*(FD/4) + t];
                f.x+=w2.x; f.y+=w2.y; f.z+=w2.z; f.w+=w2.w;
            }
            ((float4*)sm)[t] = f;
            sq[5] = d4(f, f);
#pragma unroll
            for (int off = 16; off; off >>= 1)
#pragma unroll
                for (int r = 0; r < 6; r++)
                    sq[r] += __shfl_xor_sync(0xffffffffu, sq[r], off);
            int lane = t & 31, w = t >> 5;
            if (lane == 0)
#pragma unroll
                for (int r = 0; r < 6; r++) sm[1024 + w*6 + r] = sq[r];
            __syncthreads();
            if (t < 6) {
                float s = 0.f;
                for (int w2 = 0; w2 < 8; w2++) s += sm[1024 + w2*6 + t];
                sm[1072 + t] = 1.f / sqrtf(s);
            }
            __syncthreads();
        }
        {
            int w = t >> 5, lane = t & 31;
            int iq = qc*8 + w;
            if (iq < NQ) {
                const float4* q4  = (const float4*)qf + ((size_t)b*NQ + iq)*(FD/4);
                const float4* sc4 = (const float4*)sc + (size_t)b*NWAY*(FD/4);
                const float4* f4  = (const float4*)sm;
                float qq = 0.f, d[6] = {0,0,0,0,0,0};
                for (int i = lane; i < FD/4; i += 32) {
                    float4 x = q4[i];
                    qq += d4(x, x);
#pragma unroll
                    for (int r = 0; r < NWAY; r++) d[r] += d4(x, sc4[r*(FD/4) + i]);
                    d[5] += d4(x, f4[i]);
                }
#pragma unroll
                for (int off = 16; off; off >>= 1) {
                    qq += __shfl_xor_sync(0xffffffffu, qq, off);
#pragma unroll
                    for (int r = 0; r < 6; r++) d[r] += __shfl_xor_sync(0xffffffffu, d[r], off);
                }
                if (lane == 0) {
                    float s = temp[0] / sqrtf(qq);
                    float* o = outL + ((size_t)b*NQ + iq)*6;
#pragma unroll
                    for (int r = 0; r < 6; r++) o[r] = d[r] * s * sm[1072 + r];
                }
            }
        }
        __syncthreads();
    }
}

// ---------------- host ----------------
extern "C" void kernel_launch(void* const* d_in, const int* in_sizes, int n_in,
                              void* d_out, int out_size)
{
    const float* sc   = (const float*)d_in[0];
    const float* bw   = (const float*)d_in[1];
    const float* ss   = (const float*)d_in[2];
    const float* bsm  = (const float*)d_in[3];
    const float* qf   = (const float*)d_in[4];
    const float* Wm1  = (const float*)d_in[5];
    const float* bm1  = (const float*)d_in[6];
    const float* Wm2  = (const float*)d_in[7];
    const float* bm2  = (const float*)d_in[8];
    const float* Wvis = (const float*)d_in[9];
    const float* bvis = (const float*)d_in[10];
    const float* Wsem = (const float*)d_in[11];
    const float* bsem = (const float*)d_in[12];
    const float* Wq   = (const float*)d_in[13];
    const float* Wk   = (const float*)d_in[14];
    const float* Wv   = (const float*)d_in[15];
    const float* Wqs  = (const float*)d_in[16];
    const float* Wks  = (const float*)d_in[17];
    const float* Wfc  = (const float*)d_in[18];
    const float* temp = (const float*)d_in[19];
    float* out = (float*)d_out;

    const int smem_bytes = SMEMF * sizeof(float);  // 51200
    cudaFuncSetAttribute(fused_k, cudaFuncAttributeMaxDynamicSharedMemorySize, smem_bytes);

    int dev = 0;
    cudaGetDevice(&dev);
    int nsm = 148;
    cudaDeviceGetAttribute(&nsm, cudaDevAttrMultiProcessorCount, dev);
    int bpm = 1;
    cudaOccupancyMaxActiveBlocksPerMultiprocessor(&bpm, fused_k, 256, smem_bytes);
    if (bpm < 1) bpm = 1;
    int nblk = nsm * bpm;

    void* barp = nullptr;
    cudaGetSymbolAddress(&barp, g_barrier);
    cudaMemsetAsync(barp, 0, sizeof(unsigned int), 0);

    fused_k<<<nblk, 256, smem_bytes>>>(sc, bw, ss, bsm, qf, Wm1, bm1, Wm2, bm2,
                                       Wvis, bvis, Wsem, bsem, Wq, Wk, Wv, Wqs, Wks, Wfc,
                                       temp, out);
}

// round 9
// speedup vs baseline: 2.1043x; 1.0291x over previous
#include <cuda_runtime.h>
#include <mma.h>
#include <math.h>
#include <cstdint>

using namespace nvcuda;

#define FD    1024
#define SEM   300
#define NWAY  5
#define BS    32
#define NB    512
#define NQ    75
#define BTOT  (BS*NWAY)     // 160
#define CATD  (FD+SEM)      // 1324

#define MNq   (BTOT*FD)     // 163840
#define MNk   (BTOT*CATD)   // 211840
#define SLABK (BTOT*1408)   // padded qk partial slab
#define SLABG (BS*1408)
#define SLABF (BS*FD)       // 32768

#define SMEMF 12800         // dynamic smem floats (2 x 6400 gemm buffers)
#define BUFF  6400

// ---------------- scratch ----------------
__device__ __align__(32) float g_scal[BTOT*SEM];
__device__ __align__(32) float g_gv  [BS*FD];
__device__ __align__(32) float g_gs  [BS*SEM];
__device__ __align__(32) float g_q   [BTOT*FD];
__device__ __align__(32) float g_qkg [BTOT*FD];
__device__ __align__(32) float g_qksg[BTOT*SEM];
__device__ __align__(32) float g_scr [BTOT*NB];
__device__ __align__(32) float g_avgp[4*BS*CATD];
__device__ __align__(32) float g_mixp[8*SLABF];
__device__ __align__(32) float g_part [16*MNq];
__device__ __align__(32) float g_part2[14*SLABG];
__device__ unsigned int g_barrier;

// ---------------- software grid barrier ----------------
__device__ __forceinline__ void gsync(int &gen)
{
    __syncthreads();
    if (threadIdx.x == 0) {
        __threadfence();
        atomicAdd(&g_barrier, 1u);
        unsigned target = (unsigned)gridDim.x * (unsigned)gen;
        unsigned v;
        do {
            asm volatile("ld.acquire.gpu.u32 %0, [%1];" : "=r"(v) : "l"(&g_barrier) : "memory");
            if (v >= target) break;
            __nanosleep(32);
        } while (true);
    }
    __syncthreads();
    gen++;
}

__device__ __forceinline__ float d4(float4 a, float4 b)
{ return a.x*b.x + a.y*b.y + a.z*b.z + a.w*b.w; }

// L2 evict_last access policy (created once per thread)
__device__ __forceinline__ uint64_t mkpolicy()
{
    uint64_t p;
    asm volatile("createpolicy.fractional.L2::evict_last.b64 %0, 1.0;" : "=l"(p));
    return p;
}

// evict-last vector load via cache_hint (keeps base bank L2-resident)
__device__ __forceinline__ float4 ldg_el(const float4* p, uint64_t pol)
{
    float4 v;
    asm volatile("ld.global.L2::cache_hint.v4.f32 {%0,%1,%2,%3}, [%4], %5;"
        : "=f"(v.x), "=f"(v.y), "=f"(v.z), "=f"(v.w) : "l"(p), "l"(pol));
    return v;
}

// cp.async 16B with zero-fill predicate
__device__ __forceinline__ void cp16(uint32_t saddr, const void* g, bool pred)
{
    asm volatile("cp.async.ca.shared.global [%0], [%1], 16, %2;"
        :: "r"(saddr), "l"(g), "r"(pred ? 16 : 0));
}

typedef wmma::fragment<wmma::matrix_a, 16,16,8, wmma::precision::tf32, wmma::row_major> FragA;
typedef wmma::fragment<wmma::matrix_b, 16,16,8, wmma::precision::tf32, wmma::row_major> FragBR;
typedef wmma::fragment<wmma::matrix_b, 16,16,8, wmma::precision::tf32, wmma::col_major> FragBC;
typedef wmma::fragment<wmma::accumulator, 16,16,8, float> FragC;

template<class F>
__device__ __forceinline__ void split_frag(F& hi, F& lo)
{
#pragma unroll
    for (int i = 0; i < hi.num_elements; i++) {
        float r = hi.x[i];
        float h = wmma::__float_to_tf32(r);
        hi.x[i] = h;
        lo.x[i] = wmma::__float_to_tf32(r - h);
    }
}

// ---------------- mma on one staged buffer ----------------
template<bool BTR>
__device__ __forceinline__ void mma_tile(float* As, float* Bs, int mrow, int nq,
                                         FragC& c0, FragC& c1)
{
#pragma unroll
    for (int kk = 0; kk < 32; kk += 8) {
        FragA ah, al;
        wmma::load_matrix_sync(ah, As + mrow*16*40 + kk, 40);
        split_frag(ah, al);
        if (!BTR) {
            FragBR b0h,b0l,b1h,b1l;
            wmma::load_matrix_sync(b0h, Bs + kk*136 + nq*32, 136);
            wmma::load_matrix_sync(b1h, Bs + kk*136 + nq*32 + 16, 136);
            split_frag(b0h, b0l); split_frag(b1h, b1l);
            wmma::mma_sync(c0, ah, b0h, c0);
            wmma::mma_sync(c0, ah, b0l, c0);
            wmma::mma_sync(c0, al, b0h, c0);
            wmma::mma_sync(c1, ah, b1h, c1);
            wmma::mma_sync(c1, ah, b1l, c1);
            wmma::mma_sync(c1, al, b1h, c1);
        } else {
            FragBC b0h,b0l,b1h,b1l;
            wmma::load_matrix_sync(b0h, Bs + (nq*32)*40 + kk, 40);
            wmma::load_matrix_sync(b1h, Bs + (nq*32+16)*40 + kk, 40);
            split_frag(b0h, b0l); split_frag(b1h, b1l);
            wmma::mma_sync(c0, ah, b0h, c0);
            wmma::mma_sync(c0, ah, b0l, c0);
            wmma::mma_sync(c0, al, b0h, c0);
            wmma::mma_sync(c1, ah, b1h, c1);
            wmma::mma_sync(c1, ah, b1l, c1);
            wmma::mma_sync(c1, al, b1h, c1);
        }
    }
}

// ---------------- cp.async double-buffered plain GEMM (A plain row-major) ----------------
template<bool BTR>
__device__ __forceinline__ void gemm_pipe(
    const float* __restrict__ A, int M, int K, int lda,
    const float* __restrict__ B1, const float* __restrict__ B2,
    int N1, int N, int ldb1, int ldb2,
    float* __restrict__ part, size_t slab, int ldp,
    int m0, int n0, int kt0, int kt1, float* __restrict__ smbase)
{
    const int t = threadIdx.x;
    const int warp = t >> 5, mrow = warp >> 2, nq = warp & 3;
    FragC c0, c1;
    wmma::fill_fragment(c0, 0.f);
    wmma::fill_fragment(c1, 0.f);

    auto issue = [&](int kt, int bufi) {
        float* As = smbase + bufi*BUFF;
        float* Bs = As + 1280;
        int k0 = kt*32;
        {
            int mm = t >> 3, kq = t & 7;
            int mg = m0 + mm, kg = k0 + kq*4;
            bool ok = (mg < M) && (kg < K);
            uint32_t sa = (uint32_t)__cvta_generic_to_shared(&As[mm*40 + kq*4]);
            cp16(sa, &A[(size_t)mg*lda + kg], ok);
        }
        if (!BTR) {
            int kk = t >> 3, cc = t & 7;
            int kg = k0 + kk;
#pragma unroll
            for (int j = 0; j < 4; j++) {
                int nn = (cc + 8*j)*4;
                int ng = n0 + nn;
                bool ok = (kg < K) && (ng < N);
                const float* g = (ng < N1) ? &B1[(size_t)kg*ldb1 + ng]
                                           : &B2[(size_t)kg*ldb2 + (ng - N1)];
                uint32_t sa = (uint32_t)__cvta_generic_to_shared(&Bs[kk*136 + nn]);
                cp16(sa, g, ok);
            }
        } else {
            int n = t >> 1, half = t & 1;
            int ng = n0 + n;
            bool okrow = ng < N;
            const float* brow = okrow ? ((ng < N1) ? &B1[(size_t)ng*ldb1]
                                                   : &B2[(size_t)(ng-N1)*ldb2]) : B1;
#pragma unroll
            for (int j = 0; j < 4; j++) {
                int kg = k0 + half*16 + j*4;
                bool ok = okrow && (kg < K);
                uint32_t sa = (uint32_t)__cvta_generic_to_shared(&Bs[n*40 + half*16 + j*4]);
                cp16(sa, &brow[kg], ok);
            }
        }
        asm volatile("cp.async.commit_group;");
    };

    issue(kt0, 0);
    for (int kt = kt0; kt < kt1; kt++) {
        int bufi = (kt - kt0) & 1;
        bool more = (kt + 1 < kt1);
        if (more) issue(kt + 1, bufi ^ 1);
        if (more) asm volatile("cp.async.wait_group 1;");
        else      asm volatile("cp.async.wait_group 0;");
        __syncthreads();
        float* As = smbase + bufi*BUFF;
        mma_tile<BTR>(As, As + 1280, mrow, nq, c0, c1);
        __syncthreads();
    }
    float* cb = part + slab + (size_t)(m0 + mrow*16)*ldp + n0 + nq*32;
    wmma::store_matrix_sync(cb,      c0, ldp, wmma::mem_row_major);
    wmma::store_matrix_sync(cb + 16, c1, ldp, wmma::mem_row_major);
}

// ---------------- generic GEMM with A-side reduce/gate (small stages) ----------------
template<bool REDA, bool GATEA>
__device__ __forceinline__ void gemm_w(
    const float* __restrict__ A, int M, int K, int lda,
    int Zred, size_t slabA, float ascale, const float* __restrict__ gateA,
    const float* __restrict__ B1, const float* __restrict__ B2,
    int N1, int N, int ldb1, int ldb2,
    float* __restrict__ part, size_t slab, int ldp,
    int m0, int n0, int kt0, int kt1, float* __restrict__ smbase)
{
    const int t = threadIdx.x;
    const int warp = t >> 5, mrow = warp >> 2, nq = warp & 3;
    float* As = smbase;
    float* Bs = smbase + 1280;
    FragC c0, c1;
    wmma::fill_fragment(c0, 0.f);
    wmma::fill_fragment(c1, 0.f);

    for (int kt = kt0; kt < kt1; kt++) {
        int k0 = kt*32;
        {
            int mm = t >> 3, kq = (t & 7)*4;
            int mg = m0 + mm, kg = k0 + kq;
            float4 v = make_float4(0,0,0,0);
            if (mg < M && kg + 3 < K) {
                if (REDA) {
                    for (int z = 0; z < Zred; z++) {
                        float4 w = *(const float4*)&A[(size_t)z*slabA + (size_t)mg*lda + kg];
                        v.x+=w.x; v.y+=w.y; v.z+=w.z; v.w+=w.w;
                    }
                } else v = *(const float4*)&A[(size_t)mg*lda + kg];
                v.x*=ascale; v.y*=ascale; v.z*=ascale; v.w*=ascale;
                if (GATEA) {
                    float4 g = *(const float4*)&gateA[(size_t)mg*lda + kg];
                    v.x*=g.x; v.y*=g.y; v.z*=g.z; v.w*=g.w;
                }
            } else if (mg < M) {
                float tmp[4] = {0,0,0,0};
                for (int j = 0; j < 4; j++) {
                    int k2 = kg + j;
                    if (k2 < K) {
                        float s = 0.f;
                        if (REDA) { for (int z=0; z<Zred; z++) s += A[(size_t)z*slabA + (size_t)mg*lda + k2]; }
                        else s = A[(size_t)mg*lda + k2];
                        s *= ascale;
                        if (GATEA) s *= gateA[(size_t)mg*lda + k2];
                        tmp[j] = s;
                    }
                }
                v = make_float4(tmp[0],tmp[1],tmp[2],tmp[3]);
            }
            *(float4*)&As[ (t>>3)*40 + (t&7)*4 ] = v;
        }
        {
            int kk = t >> 3, cc = t & 7;
            int kg = k0 + kk;
#pragma unroll
            for (int j = 0; j < 4; j++) {
                int nn = (cc + 8*j)*4;
                int ng = n0 + nn;
                float4 v = make_float4(0,0,0,0);
                if (kg < K && ng < N) {
                    if (ng < N1) v = *(const float4*)&B1[(size_t)kg*ldb1 + ng];
                    else         v = *(const float4*)&B2[(size_t)kg*ldb2 + (ng-N1)];
                }
                *(float4*)&Bs[kk*136 + nn] = v;
            }
        }
        __syncthreads();
        mma_tile<false>(As, Bs, mrow, nq, c0, c1);
        __syncthreads();
    }
    float* cb = part + slab + (size_t)(m0 + mrow*16)*ldp + n0 + nq*32;
    wmma::store_matrix_sync(cb,      c0, ldp, wmma::mem_row_major);
    wmma::store_matrix_sync(cb + 16, c1, ldp, wmma::mem_row_major);
}

// stage unit counts (avg moved next to its consumers for L2 retention)
#define U_MLP   40
#define U_QP1   320
#define S0U     (U_MLP+U_QP1)     // 360
#define U_QP2   200
#define U_AVG   256
#define S1U     (U_QP2+U_AVG)     // 456
#define U_QR    160
#define U_GATP  154
#define S2U     (U_QR+U_GATP)     // 314
#define U_GR    166
#define U_QK    440
#define S3U     (U_GR+U_QK)       // 606

__global__ void __launch_bounds__(256, 2) fused_k(
    const float* __restrict__ sc,  const float* __restrict__ bw,
    const float* __restrict__ ss,  const float* __restrict__ bsm,
    const float* __restrict__ qf,
    const float* __restrict__ Wm1, const float* __restrict__ bm1,
    const float* __restrict__ Wm2, const float* __restrict__ bm2,
    const float* __restrict__ Wvis,const float* __restrict__ bvis,
    const float* __restrict__ Wsem,const float* __restrict__ bsem,
    const float* __restrict__ Wq,  const float* __restrict__ Wk,
    const float* __restrict__ Wv,  const float* __restrict__ Wqs,
    const float* __restrict__ Wks, const float* __restrict__ Wfc,
    const float* __restrict__ temp, float* __restrict__ outL)
{
    extern __shared__ __align__(32) float sm[];
    const int NBLK = gridDim.x;
    const int t = threadIdx.x;
    const uint64_t pol = mkpolicy();
    int gen = 1;

    // ===== S0: MLP | qp1 (sc@Wq, pipelined) =====
    for (int u = blockIdx.x; u < S0U; u += NBLK) {
        if (u < U_MLP) {
            int m0u = u * 4;
            for (int i = t; i < 4*SEM; i += 256)
                sm[i] = ss[(size_t)(m0u + i/SEM)*SEM + (i % SEM)];
            __syncthreads();
            for (int n = t; n < SEM; n += 256) {
                float a0 = bm1[n], a1 = a0, a2 = a0, a3 = a0;
                for (int k = 0; k < SEM; k++) {
                    float w = Wm1[(size_t)k*SEM + n];
                    a0 = fmaf(sm[0*SEM+k], w, a0); a1 = fmaf(sm[1*SEM+k], w, a1);
                    a2 = fmaf(sm[2*SEM+k], w, a2); a3 = fmaf(sm[3*SEM+k], w, a3);
                }
                sm[1280 + 0*SEM + n] = (a0 >= 0.f) ? a0 : 0.1f*a0;
                sm[1280 + 1*SEM + n] = (a1 >= 0.f) ? a1 : 0.1f*a1;
                sm[1280 + 2*SEM + n] = (a2 >= 0.f) ? a2 : 0.1f*a2;
                sm[1280 + 3*SEM + n] = (a3 >= 0.f) ? a3 : 0.1f*a3;
            }
            __syncthreads();
            for (int n = t; n < SEM; n += 256) {
                float a0 = bm2[n], a1 = a0, a2 = a0, a3 = a0;
                for (int k = 0; k < SEM; k++) {
                    float w = Wm2[(size_t)k*SEM + n];
                    a0 = fmaf(sm[1280+0*SEM+k], w, a0); a1 = fmaf(sm[1280+1*SEM+k], w, a1);
                    a2 = fmaf(sm[1280+2*SEM+k], w, a2); a3 = fmaf(sm[1280+3*SEM+k], w, a3);
                }
                g_scal[(size_t)(m0u+0)*SEM + n] = a0;
                g_scal[(size_t)(m0u+1)*SEM + n] = a1;
                g_scal[(size_t)(m0u+2)*SEM + n] = a2;
                g_scal[(size_t)(m0u+3)*SEM + n] = a3;
            }
            __syncthreads();
        } else {
            int uu = u - U_MLP;
            int z = uu & 7, r = uu >> 3;
            int nt = r & 7, mt = r >> 3;
            gemm_pipe<false>(sc, BTOT, FD, FD, Wq, Wq, FD, FD, FD, FD,
                g_part, (size_t)z*MNq, FD, mt*32, nt*128, z*4, z*4+4, sm);
        }
    }
    gsync(gen);

    // ===== S1: qp2 (s@Wqs, pipelined) | avg partials (evict_last bank read) =====
    for (int u = blockIdx.x; u < S1U; u += NBLK) {
        if (u < U_QP2) {
            int z = u % 5, r = u / 5;
            int nt = r & 7, mt = r >> 3;
            gemm_pipe<false>(g_scal, BTOT, SEM, SEM, Wqs, Wqs, FD, FD, FD, FD,
                g_part, (size_t)(8+z)*MNq, FD, mt*32, nt*128, z*2, z*2+2, sm);
        } else {
            int uu = u - U_QP2;
            int chunk = uu >> 6, r = uu & 63;
            int b = r >> 1, cpart = r & 1;
            int c4 = cpart*256 + t;
            if (c4 < CATD/4) {
                int c = c4*4;
                int n0 = chunk*128;
                float4 v = make_float4(0,0,0,0);
                if (c < FD) {
                    const float4* p = (const float4*)bw + ((size_t)b*NB + n0)*(FD/4) + c4;
#pragma unroll 16
                    for (int n = 0; n < 128; n++) {
                        float4 x = ldg_el(&p[(size_t)n*(FD/4)], pol);
                        v.x+=x.x; v.y+=x.y; v.z+=x.z; v.w+=x.w;
                    }
                } else {
                    const float4* p = (const float4*)(bsm + ((size_t)b*NB + n0)*SEM + (c-FD));
#pragma unroll 16
                    for (int n = 0; n < 128; n++) {
                        float4 x = ldg_el(&p[(size_t)n*(SEM/4)], pol);
                        v.x+=x.x; v.y+=x.y; v.z+=x.z; v.w+=x.w;
                    }
                }
                *(float4*)&g_avgp[(size_t)chunk*BS*CATD + (size_t)b*CATD + c] = v;
            }
        }
    }
    gsync(gen);

    // ===== S2: q reduce | gates GEMM partials =====
    for (int u = blockIdx.x; u < S2U; u += NBLK) {
        if (u < U_QR) {
            size_t i4 = (size_t)u*256 + t;
            float4 v = make_float4(0,0,0,0);
#pragma unroll
            for (int z = 0; z < 13; z++) {
                float4 w = ((const float4*)g_part)[(size_t)z*(MNq/4) + i4];
                v.x+=w.x; v.y+=w.y; v.z+=w.z; v.w+=w.w;
            }
            ((float4*)g_q)[i4] = v;
        } else {
            int uu = u - U_QR;
            int z = uu % 14, nt = uu / 14;
            gemm_w<true,false>(g_avgp, BS, CATD, CATD, 4, (size_t)BS*CATD, 1.f/NB, nullptr,
                Wvis, Wsem, FD, CATD, FD, SEM,
                g_part2, (size_t)z*SLABG, 1408, 0, nt*128, z*3, z*3+3, sm);
        }
    }
    gsync(gen);

    // ===== S3: gates reduce | qk GEMM (q @ [Wk;Wks]^T, pipelined BTR) =====
    for (int u = blockIdx.x; u < S3U; u += NBLK) {
        if (u < U_GR) {
            size_t i = (size_t)u*256 + t;
            if (i < (size_t)BS*CATD) {
                int m = (int)(i / CATD), n = (int)(i % CATD);
                float v = 0.f;
#pragma unroll
                for (int z = 0; z < 14; z++) v += g_part2[(size_t)z*SLABG + (size_t)m*1408 + n];
                if (n < FD) {
                    v += bvis[n];
                    g_gv[(size_t)m*FD + n] = 1.f + 1.f/(1.f + __expf(-v));
                } else {
                    v += bsem[n - FD];
                    g_gs[(size_t)m*SEM + (n - FD)] = 1.f + 1.f/(1.f + __expf(-v));
                }
            }
        } else {
            int uu = u - U_GR;
            int z = uu & 7, r = uu >> 3;
            int nt = r % 11, mt = r / 11;
            gemm_pipe<true>(g_q, BTOT, FD, FD, Wk, Wks, FD, CATD, FD, FD,
                g_part, (size_t)z*SLABK, 1408, mt*32, nt*128, z*4, z*4+4, sm);
        }
    }
    gsync(gen);

    // ===== S4: qk reduce * gates =====
    for (int u = blockIdx.x; u < 828; u += NBLK) {
        size_t i = (size_t)u*256 + t;
        if (i < (size_t)MNk) {
            int m = (int)(i / CATD), n = (int)(i % CATD);
            float v = 0.f;
#pragma unroll
            for (int z = 0; z < 8; z++) v += g_part[(size_t)z*SLABK + (size_t)m*1408 + n];
            int b = m / NWAY;
            if (n < FD) g_qkg [(size_t)m*FD  + n]      = v * g_gv[(size_t)b*FD  + n];
            else        g_qksg[(size_t)m*SEM + (n-FD)] = v * g_gs[(size_t)b*SEM + (n-FD)];
        }
    }
    gsync(gen);

    // ===== S5: scores (bank should now be L2-resident) =====
    for (int u = blockIdx.x; u < 512; u += NBLK) {
        int b = u / 16, ch = u % 16;
        int w = t >> 5, lane = t & 31;
        int nbase = ch*32 + w*4;
        float acc[4][5];
#pragma unroll
        for (int j = 0; j < 4; j++)
#pragma unroll
            for (int p = 0; p < 5; p++) acc[j][p] = 0.f;
        const float4* qkg4 = (const float4*)g_qkg  + (size_t)b*NWAY*(FD/4);
        const float4* qks4 = (const float4*)g_qksg + (size_t)b*NWAY*(SEM/4);
        const float4* bw4  = (const float4*)bw     + (size_t)b*NB*(FD/4);
        const float4* bs4  = (const float4*)bsm    + (size_t)b*NB*(SEM/4);
#pragma unroll
        for (int tt = 0; tt < 8; tt++) {
            int c = tt*32 + lane;
            float4 qv[5];
#pragma unroll
            for (int p = 0; p < 5; p++) qv[p] = qkg4[p*(FD/4) + c];
#pragma unroll
            for (int j = 0; j < 4; j++) {
                float4 x = ldg_el(&bw4[(size_t)(nbase+j)*(FD/4) + c], pol);
#pragma unroll
                for (int p = 0; p < 5; p++) acc[j][p] += d4(x, qv[p]);
            }
        }
#pragma unroll
        for (int tt = 0; tt < 3; tt++) {
            int c = tt*32 + lane;
            bool ok = c < (SEM/4);
            float4 qv[5];
#pragma unroll
            for (int p = 0; p < 5; p++)
                qv[p] = ok ? qks4[p*(SEM/4) + c] : make_float4(0,0,0,0);
#pragma unroll
            for (int j = 0; j < 4; j++) {
                float4 x = ok ? ldg_el(&bs4[(size_t)(nbase+j)*(SEM/4) + c], pol) : make_float4(0,0,0,0);
#pragma unroll
                for (int p = 0; p < 5; p++) acc[j][p] += d4(x, qv[p]);
            }
        }
#pragma unroll
        for (int off = 16; off; off >>= 1)
#pragma unroll
            for (int j = 0; j < 4; j++)
#pragma unroll
                for (int p = 0; p < 5; p++)
                    acc[j][p] += __shfl_xor_sync(0xffffffffu, acc[j][p], off);
#pragma unroll
        for (int j = 0; j < 4; j++)
            if (lane == j) {
                int n = nbase + j;
#pragma unroll
                for (int p = 0; p < 5; p++)
                    g_scr[(size_t)(b*NWAY+p)*NB + n] = acc[j][p] * (1.f/32.f);
            }
    }
    gsync(gen);

    // ===== S6: fused softmax + nway-avg attention + mix partials (256 units) =====
    for (int u = blockIdx.x; u < 256; u += NBLK) {
        int b = u >> 3, chunk = u & 7;
        int n0 = chunk*64;
        int w = t >> 5, lane = t & 31;
        for (int i = t; i < NWAY*NB; i += 256)
            sm[i] = g_scr[(size_t)b*NWAY*NB + i];
        __syncthreads();
        float mx[5];
#pragma unroll
        for (int p = 0; p < 5; p++)
            mx[p] = fmaxf(sm[p*NB + t], sm[p*NB + 256 + t]);
#pragma unroll
        for (int off = 16; off; off >>= 1)
#pragma unroll
            for (int p = 0; p < 5; p++)
                mx[p] = fmaxf(mx[p], __shfl_xor_sync(0xffffffffu, mx[p], off));
        if (lane == 0)
#pragma unroll
            for (int p = 0; p < 5; p++) sm[2624 + w*5 + p] = mx[p];
        __syncthreads();
        if (t < 5) {
            float m = sm[2624 + t];
            for (int w2 = 1; w2 < 8; w2++) m = fmaxf(m, sm[2624 + w2*5 + t]);
            sm[2680 + t] = m;
        }
        __syncthreads();
        float sme[5];
#pragma unroll
        for (int p = 0; p < 5; p++) {
            float m = sm[2680 + p];
            sme[p] = __expf(sm[p*NB + t] - m) + __expf(sm[p*NB + 256 + t] - m);
        }
#pragma unroll
        for (int off = 16; off; off >>= 1)
#pragma unroll
            for (int p = 0; p < 5; p++)
                sme[p] += __shfl_xor_sync(0xffffffffu, sme[p], off);
        if (lane == 0)
#pragma unroll
            for (int p = 0; p < 5; p++) sm[2624 + w*5 + p] = sme[p];
        __syncthreads();
        if (t < 5) {
            float s = 0.f;
            for (int w2 = 0; w2 < 8; w2++) s += sm[2624 + w2*5 + t];
            sm[2688 + t] = 1.f / s;
        }
        __syncthreads();
        if (t < 64) {
            int n = n0 + t;
            float a = 0.f;
#pragma unroll
            for (int p = 0; p < 5; p++)
                a += __expf(sm[p*NB + n] - sm[2680 + p]) * sm[2688 + p];
            sm[2696 + t] = a * (1.f/NWAY);
        }
        __syncthreads();
        float4 acc = make_float4(0,0,0,0);
        const float4* p4 = (const float4*)bw + ((size_t)b*NB + n0)*(FD/4) + t;
#pragma unroll 16
        for (int r = 0; r < 64; r++) {
            float4 x = p4[(size_t)r*(FD/4)];
            float a = sm[2696 + r];
            acc.x = fmaf(x.x, a, acc.x); acc.y = fmaf(x.y, a, acc.y);
            acc.z = fmaf(x.z, a, acc.z); acc.w = fmaf(x.w, a, acc.w);
        }
        ((float4*)g_mixp)[(size_t)chunk*(SLABF/4) + (size_t)b*(FD/4) + t] = acc;
        __syncthreads();
    }
    gsync(gen);

    // ===== S7: fakev = (mixavg * gv) @ Wv, split-K 16 =====
    for (int u = blockIdx.x; u < 128; u += NBLK) {
        int z = u & 15, nt = u >> 4;
        gemm_w<true,true>(g_mixp, BS, FD, FD, 8, (size_t)SLABF, 1.f, g_gv,
            Wv, Wv, FD, FD, FD, FD,
            g_part, (size_t)z*SLABF, FD, 0, nt*128, z*2, z*2+2, sm);
    }
    gsync(gen);

    // ===== S8: fakefc = reduce(fakev) @ Wfc, split-K 16 =====
    for (int u = blockIdx.x; u < 128; u += NBLK) {
        int z = u & 15, nt = u >> 4;
        gemm_w<true,false>(g_part, BS, FD, FD, 16, (size_t)SLABF, 1.f, nullptr,
            Wfc, Wfc, FD, FD, FD, FD,
            g_part, (size_t)(16+z)*SLABF, FD, 0, nt*128, z*2, z*2+2, sm);
    }
    gsync(gen);

    // ===== S9: fake + norms + logits =====
    for (int u = blockIdx.x; u < BS*10; u += NBLK) {
        int b = u / 10, qc = u % 10;
        {
            const float4* sc4 = (const float4*)sc + (size_t)b*NWAY*(FD/4);
            float4 f = make_float4(0,0,0,0);
            float sq[6];
#pragma unroll
            for (int c = 0; c < NWAY; c++) {
                float4 o = sc4[c*(FD/4) + t];
                sq[c] = d4(o, o);
                f.x+=o.x; f.y+=o.y; f.z+=o.z; f.w+=o.w;
            }
            f.x*=0.2f; f.y*=0.2f; f.z*=0.2f; f.w*=0.2f;
#pragma unroll
            for (int z = 16; z < 32; z++) {
                float4 w2 = ((const float4*)g_part)[(size_t)z*(SLABF/4) + (size_t)b*(FD/4) + t];
                f.x+=w2.x; f.y+=w2.y; f.z+=w2.z; f.w+=w2.w;
            }
            ((float4*)sm)[t] = f;
            sq[5] = d4(f, f);
#pragma unroll
            for (int off = 16; off; off >>= 1)
#pragma unroll
                for (int r = 0; r < 6; r++)
                    sq[r] += __shfl_xor_sync(0xffffffffu, sq[r], off);
            int lane = t & 31, w = t >> 5;
            if (lane == 0)
#pragma unroll
                for (int r = 0; r < 6; r++) sm[1024 + w*6 + r] = sq[r];
            __syncthreads();
            if (t < 6) {
                float s = 0.f;
                for (int w2 = 0; w2 < 8; w2++) s += sm[1024 + w2*6 + t];
                sm[1072 + t] = 1.f / sqrtf(s);
            }
            __syncthreads();
        }
        {
            int w = t >> 5, lane = t & 31;
            int iq = qc*8 + w;
            if (iq < NQ) {
                const float4* q4  = (const float4*)qf + ((size_t)b*NQ + iq)*(FD/4);
                const float4* sc4 = (const float4*)sc + (size_t)b*NWAY*(FD/4);
                const float4* f4  = (const float4*)sm;
                float qq = 0.f, d[6] = {0,0,0,0,0,0};
                for (int i = lane; i < FD/4; i += 32) {
                    float4 x = q4[i];
                    qq += d4(x, x);
#pragma unroll
                    for (int r = 0; r < NWAY; r++) d[r] += d4(x, sc4[r*(FD/4) + i]);
                    d[5] += d4(x, f4[i]);
                }
#pragma unroll
                for (int off = 16; off; off >>= 1) {
                    qq += __shfl_xor_sync(0xffffffffu, qq, off);
#pragma unroll
                    for (int r = 0; r < 6; r++) d[r] += __shfl_xor_sync(0xffffffffu, d[r], off);
                }
                if (lane == 0) {
                    float s = temp[0] / sqrtf(qq);
                    float* o = outL + ((size_t)b*NQ + iq)*6;
#pragma unroll
                    for (int r = 0; r < 6; r++) o[r] = d[r] * s * sm[1072 + r];
                }
            }
        }
        __syncthreads();
    }
}

// ---------------- host ----------------
extern "C" void kernel_launch(void* const* d_in, const int* in_sizes, int n_in,
                              void* d_out, int out_size)
{
    const float* sc   = (const float*)d_in[0];
    const float* bw   = (const float*)d_in[1];
    const float* ss   = (const float*)d_in[2];
    const float* bsm  = (const float*)d_in[3];
    const float* qf   = (const float*)d_in[4];
    const float* Wm1  = (const float*)d_in[5];
    const float* bm1  = (const float*)d_in[6];
    const float* Wm2  = (const float*)d_in[7];
    const float* bm2  = (const float*)d_in[8];
    const float* Wvis = (const float*)d_in[9];
    const float* bvis = (const float*)d_in[10];
    const float* Wsem = (const float*)d_in[11];
    const float* bsem = (const float*)d_in[12];
    const float* Wq   = (const float*)d_in[13];
    const float* Wk   = (const float*)d_in[14];
    const float* Wv   = (const float*)d_in[15];
    const float* Wqs  = (const float*)d_in[16];
    const float* Wks  = (const float*)d_in[17];
    const float* Wfc  = (const float*)d_in[18];
    const float* temp = (const float*)d_in[19];
    float* out = (float*)d_out;

    const int smem_bytes = SMEMF * sizeof(float);  // 51200
    cudaFuncSetAttribute(fused_k, cudaFuncAttributeMaxDynamicSharedMemorySize, smem_bytes);

    int dev = 0;
    cudaGetDevice(&dev);
    int nsm = 148;
    cudaDeviceGetAttribute(&nsm, cudaDevAttrMultiProcessorCount, dev);
    int bpm = 1;
    cudaOccupancyMaxActiveBlocksPerMultiprocessor(&bpm, fused_k, 256, smem_bytes);
    if (bpm < 1) bpm = 1;
    int nblk = nsm * bpm;

    void* barp = nullptr;
    cudaGetSymbolAddress(&barp, g_barrier);
    cudaMemsetAsync(barp, 0, sizeof(unsigned int), 0);

    fused_k<<<nblk, 256, smem_bytes>>>(sc, bw, ss, bsm, qf, Wm1, bm1, Wm2, bm2,
                                       Wvis, bvis, Wsem, bsem, Wq, Wk, Wv, Wqs, Wks, Wfc,
                                       temp, out);
}